// round 9
// baseline (speedup 1.0000x reference)
#include <cuda_runtime.h>
#include <cuda_bf16.h>
#include <cstdint>
#include <math.h>

// Problem constants
#define BB 8
#define SS 2048
#define DD 512
#define UU 512

#define NX ((size_t)BB * SS * DD)      // 8388608
#define NW ((size_t)DD * UU)           // 262144
#define NA ((size_t)BB * SS * SS)      // 33554432

#define SCALE 0.04419417382415922f    // 1/sqrt(512)

// ---------------------------------------------------------------------------
// Device-global scratch (no allocations allowed)
// ---------------------------------------------------------------------------
__device__ __align__(128) __nv_bfloat16 g_xh[NX],  g_xl[NX];     // x splits [B*S][D]
__device__ __align__(128) __nv_bfloat16 g_wqh[NW], g_wql[NW];    // Wq splits [D][U]
__device__ __align__(128) __nv_bfloat16 g_wkh[NW], g_wkl[NW];    // Wk splits [D][U]
__device__ __align__(128) __nv_bfloat16 g_wvth[NW], g_wvtl[NW];  // Wv^T splits [U][D]
__device__ __align__(128) __nv_bfloat16 g_mth[NW], g_mtl[NW];    // Mt = scale*Wk Wq^T [D][D]
__device__ __align__(128) __nv_bfloat16 g_ph[NX],  g_pl[NX];     // P = x Mt^T [B*S][D]
__device__ __align__(128) __nv_bfloat16 g_vth[NX], g_vtl[NX];    // V^T splits [B][U][S]
__device__ __align__(128) __nv_bfloat16 g_ah[NA],  g_al[NA];     // attn splits [B][S][S]

// ---------------------------------------------------------------------------
// Helpers
// ---------------------------------------------------------------------------
__device__ __forceinline__ uint32_t smem_u32(const void* p) {
    uint32_t a;
    asm("{ .reg .u64 t; cvta.to.shared.u64 t, %1; cvt.u32.u64 %0, t; }" : "=r"(a) : "l"(p));
    return a;
}
__device__ __forceinline__ uint32_t pack_bf2(__nv_bfloat16 a, __nv_bfloat16 b) {
    return (uint32_t)__bfloat16_as_ushort(a) | ((uint32_t)__bfloat16_as_ushort(b) << 16);
}

#define LDSM4(r0, r1, r2, r3, addr) \
    asm volatile("ldmatrix.sync.aligned.m8n8.x4.shared.b16 {%0,%1,%2,%3}, [%4];" \
        : "=r"(r0), "=r"(r1), "=r"(r2), "=r"(r3) : "r"(addr))

#define MMA16816(d, a, b) \
    asm volatile("mma.sync.aligned.m16n8k16.row.col.f32.bf16.bf16.f32 " \
        "{%0,%1,%2,%3}, {%4,%5,%6,%7}, {%8,%9}, {%0,%1,%2,%3};" \
        : "+f"((d)[0]), "+f"((d)[1]), "+f"((d)[2]), "+f"((d)[3]) \
        : "r"((a)[0]), "r"((a)[1]), "r"((a)[2]), "r"((a)[3]), \
          "r"((b)[0]), "r"((b)[1]))

// ---------------------------------------------------------------------------
// bf16x3 mma GEMM: 256x128 CTA tile, BK=32, 256 threads (8 warps as 4x2,
// 64x64 warp tile), 3-stage cp.async pipeline, 1 CTA/SM.  ALL operands K-major:
//   A: MxK row-major (hi/lo), B: NxK row-major (hi/lo).  C = A * B^T.
// MODE 0: fp32 store.  MODE 1: alpha-scaled bf16 hi/lo split store.
// MODE 2: bf16 hi/lo split TRANSPOSED store (per-batch V^T layout).
// ---------------------------------------------------------------------------
#define A_ARR 20480                     // 256 rows * 80 bytes
#define B_ARR 10240                     // 128 rows * 80 bytes
#define STG_B (2 * A_ARR + 2 * B_ARR)   // 61440 per stage
#define SMEM_DYN (3 * STG_B)            // 184320 bytes

template <int ROWS>
__device__ __forceinline__ void stage_arr(uint32_t sdst, const __nv_bfloat16* __restrict__ src,
                                          int r0, int k0, int ld, int tid) {
#pragma unroll
    for (int j = 0; j < ROWS / 64; j++) {
        int idx = tid + j * 256;                  // ROWS*4 chunks of 16B
        int r = idx >> 2, c = idx & 3;
        uint32_t dst = sdst + (uint32_t)(r * 80 + c * 16);
        const void* gp = (const void*)(src + (size_t)(r0 + r) * ld + k0 + c * 8);
        asm volatile("cp.async.cg.shared.global [%0], [%1], 16;" :: "r"(dst), "l"(gp));
    }
}

__device__ __forceinline__ void stage_all(uint32_t sb,
                                          const __nv_bfloat16* Ah, const __nv_bfloat16* Al,
                                          const __nv_bfloat16* Bh, const __nv_bfloat16* Bl,
                                          int row0, int col0, int k0, int lda, int ldb, int tid) {
    stage_arr<256>(sb,                     Ah, row0, k0, lda, tid);
    stage_arr<256>(sb + A_ARR,             Al, row0, k0, lda, tid);
    stage_arr<128>(sb + 2 * A_ARR,         Bh, col0, k0, ldb, tid);
    stage_arr<128>(sb + 2 * A_ARR + B_ARR, Bl, col0, k0, ldb, tid);
    asm volatile("cp.async.commit_group;" ::: "memory");
}

template <int MODE>
__device__ __forceinline__ void gemm_mma(int row0, int col0,
                                         const __nv_bfloat16* __restrict__ Ah,
                                         const __nv_bfloat16* __restrict__ Al,
                                         const __nv_bfloat16* __restrict__ Bh,
                                         const __nv_bfloat16* __restrict__ Bl,
                                         int K, int lda, int ldb, float alpha,
                                         float* __restrict__ Cf, int ldc,
                                         __nv_bfloat16* __restrict__ Oh,
                                         __nv_bfloat16* __restrict__ Ol, int ldo) {
    extern __shared__ __nv_bfloat16 smem[];

    const int tid  = threadIdx.x;
    const int warp = tid >> 5;
    const int lane = tid & 31;
    const int wm = (warp >> 1) * 64;     // warp row: 0/64/128/192
    const int wn = (warp & 1) * 64;      // warp col: 0/64

    const uint32_t sbase = smem_u32(smem);

    // Per-lane ldmatrix byte offsets within an array.
    const uint32_t aLane = (uint32_t)((wm + ((lane >> 3) & 1) * 8 + (lane & 7)) * 80
                                      + (lane >> 4) * 16);
    const uint32_t bLane = (uint32_t)((wn + ((lane >> 4) & 1) * 8 + (lane & 7)) * 80
                                      + ((lane >> 3) & 1) * 16);

    float acc[4][8][4];                  // [i m16][j n8][4]
#pragma unroll
    for (int i = 0; i < 4; i++)
#pragma unroll
        for (int j = 0; j < 8; j++)
#pragma unroll
            for (int e = 0; e < 4; e++) acc[i][j][e] = 0.0f;

    const int niter = K >> 5;

    // prologue: stage iters 0,1
    stage_all(sbase, Ah, Al, Bh, Bl, row0, col0, 0, lda, ldb, tid);
    stage_all(sbase + STG_B, Ah, Al, Bh, Bl, row0, col0, 32, lda, ldb, tid);

    int buf = 0;
    for (int it = 0; it < niter; it++) {
        if (it + 1 < niter) {
            asm volatile("cp.async.wait_group 1;" ::: "memory");
        } else {
            asm volatile("cp.async.wait_group 0;" ::: "memory");
        }
        __syncthreads();
        if (it + 2 < niter) {
            int nb = buf + 2; if (nb >= 3) nb -= 3;
            stage_all(sbase + (uint32_t)(nb * STG_B), Ah, Al, Bh, Bl,
                      row0, col0, (it + 2) << 5, lda, ldb, tid);
        }

        const uint32_t base = sbase + (uint32_t)(buf * STG_B);
        const uint32_t pAh = base + aLane;
        const uint32_t pAl = base + A_ARR + aLane;
        const uint32_t pBh = base + 2 * A_ARR + bLane;
        const uint32_t pBl = base + 2 * A_ARR + B_ARR + bLane;

#pragma unroll
        for (int ks = 0; ks < 2; ks++) {
            const uint32_t ko = ks * 32;         // 16 halves = 32 bytes
            uint32_t ah[4][4], al[4][4];
#pragma unroll
            for (int i = 0; i < 4; i++) {
                LDSM4(ah[i][0], ah[i][1], ah[i][2], ah[i][3], pAh + i * 1280 + ko);
                LDSM4(al[i][0], al[i][1], al[i][2], al[i][3], pAl + i * 1280 + ko);
            }
#pragma unroll
            for (int h = 0; h < 2; h++) {        // n32 halves of the 64-wide warp tile
                uint32_t bh[4][2], bl[4][2];
#pragma unroll
                for (int jpp = 0; jpp < 2; jpp++) {
                    int jp = h * 2 + jpp;        // n16 group
                    LDSM4(bh[2 * jpp][0], bh[2 * jpp][1], bh[2 * jpp + 1][0], bh[2 * jpp + 1][1],
                          pBh + jp * 1280 + ko);
                    LDSM4(bl[2 * jpp][0], bl[2 * jpp][1], bl[2 * jpp + 1][0], bl[2 * jpp + 1][1],
                          pBl + jp * 1280 + ko);
                }
                // term-major: 16 independent MMAs between same-acc reuses
#pragma unroll
                for (int i = 0; i < 4; i++)
#pragma unroll
                    for (int jj = 0; jj < 4; jj++) MMA16816(acc[i][h * 4 + jj], ah[i], bh[jj]);
#pragma unroll
                for (int i = 0; i < 4; i++)
#pragma unroll
                    for (int jj = 0; jj < 4; jj++) MMA16816(acc[i][h * 4 + jj], ah[i], bl[jj]);
#pragma unroll
                for (int i = 0; i < 4; i++)
#pragma unroll
                    for (int jj = 0; jj < 4; jj++) MMA16816(acc[i][h * 4 + jj], al[i], bh[jj]);
            }
        }
        buf++; if (buf == 3) buf = 0;
    }

    // ------------------------- epilogue -------------------------
    // acc frag layout: c0:(m=lane/4, n=2(lane%4)) c1:(m,n+1) c2:(m+8,n) c3:(m+8,n+1)
    const int er = lane >> 2;
    const int ec = (lane & 3) * 2;

    if constexpr (MODE == 0) {
#pragma unroll
        for (int i = 0; i < 4; i++)
#pragma unroll
            for (int j = 0; j < 8; j++) {
                size_t r = (size_t)(row0 + wm + i * 16 + er);
                int c = col0 + wn + j * 8 + ec;
                *reinterpret_cast<float2*>(&Cf[r * ldc + c]) =
                    make_float2(acc[i][j][0], acc[i][j][1]);
                *reinterpret_cast<float2*>(&Cf[(r + 8) * ldc + c]) =
                    make_float2(acc[i][j][2], acc[i][j][3]);
            }
    } else {
        __syncthreads();   // pipeline smem reuse: all warps done reading stages
        float* ew = (float*)(smem + warp * 768);   // 16x24 floats = 1536 B per warp
#pragma unroll
        for (int i = 0; i < 4; i++)
#pragma unroll
            for (int jp = 0; jp < 4; jp++) {
                int j0 = 2 * jp, j1 = 2 * jp + 1;
                ew[er * 24 + ec]            = acc[i][j0][0];
                ew[er * 24 + ec + 1]        = acc[i][j0][1];
                ew[(er + 8) * 24 + ec]      = acc[i][j0][2];
                ew[(er + 8) * 24 + ec + 1]  = acc[i][j0][3];
                ew[er * 24 + 8 + ec]        = acc[i][j1][0];
                ew[er * 24 + 8 + ec + 1]    = acc[i][j1][1];
                ew[(er + 8) * 24 + 8 + ec]     = acc[i][j1][2];
                ew[(er + 8) * 24 + 8 + ec + 1] = acc[i][j1][3];
                __syncwarp();
                if constexpr (MODE == 1) {
                    int r = lane >> 1, cb = (lane & 1) * 8;
                    float v[8];
#pragma unroll
                    for (int e = 0; e < 8; e++) v[e] = ew[r * 24 + cb + e] * alpha;
                    uint4 hp, lp;
                    __nv_bfloat16 h[8];
#pragma unroll
                    for (int e = 0; e < 8; e++) h[e] = __float2bfloat16(v[e]);
                    hp.x = pack_bf2(h[0], h[1]); hp.y = pack_bf2(h[2], h[3]);
                    hp.z = pack_bf2(h[4], h[5]); hp.w = pack_bf2(h[6], h[7]);
                    __nv_bfloat16 l[8];
#pragma unroll
                    for (int e = 0; e < 8; e++) l[e] = __float2bfloat16(v[e] - __bfloat162float(h[e]));
                    lp.x = pack_bf2(l[0], l[1]); lp.y = pack_bf2(l[2], l[3]);
                    lp.z = pack_bf2(l[4], l[5]); lp.w = pack_bf2(l[6], l[7]);
                    size_t idx = (size_t)(row0 + wm + i * 16 + r) * ldo + col0 + wn + jp * 16 + cb;
                    *reinterpret_cast<uint4*>(&Oh[idx]) = hp;
                    *reinterpret_cast<uint4*>(&Ol[idx]) = lp;
                } else {
                    // MODE 2: transposed split (V^T), row0 indexes tokens [B*S]
                    const int b  = row0 >> 11;               // SS == 2048
                    const int s0 = (row0 & 2047) + wm + i * 16;
                    __nv_bfloat16* ohb = Oh + (size_t)b * UU * SS;
                    __nv_bfloat16* olb = Ol + (size_t)b * UU * SS;
                    if (lane < 16) {
                        int u = lane;
                        float v[16];
#pragma unroll
                        for (int r = 0; r < 16; r++) v[r] = ew[r * 24 + u];
                        uint32_t hw[8], lw[8];
#pragma unroll
                        for (int e = 0; e < 8; e++) {
                            __nv_bfloat16 ha = __float2bfloat16(v[2 * e]);
                            __nv_bfloat16 hb = __float2bfloat16(v[2 * e + 1]);
                            hw[e] = pack_bf2(ha, hb);
                            lw[e] = pack_bf2(__float2bfloat16(v[2 * e] - __bfloat162float(ha)),
                                             __float2bfloat16(v[2 * e + 1] - __bfloat162float(hb)));
                        }
                        size_t idx = (size_t)(col0 + wn + jp * 16 + u) * (size_t)ldo + s0;
                        uint4 h0, h1, l0, l1;
                        h0.x = hw[0]; h0.y = hw[1]; h0.z = hw[2]; h0.w = hw[3];
                        h1.x = hw[4]; h1.y = hw[5]; h1.z = hw[6]; h1.w = hw[7];
                        l0.x = lw[0]; l0.y = lw[1]; l0.z = lw[2]; l0.w = lw[3];
                        l1.x = lw[4]; l1.y = lw[5]; l1.z = lw[6]; l1.w = lw[7];
                        *reinterpret_cast<uint4*>(&ohb[idx])     = h0;
                        *reinterpret_cast<uint4*>(&ohb[idx + 8]) = h1;
                        *reinterpret_cast<uint4*>(&olb[idx])     = l0;
                        *reinterpret_cast<uint4*>(&olb[idx + 8]) = l1;
                    }
                }
                __syncwarp();
            }
    }
}

// ---------------------------------------------------------------------------
// GEMM kernel wrappers
// ---------------------------------------------------------------------------

// Combined V^T projection (blocks 0..255) + Mt (blocks 256..263).
__global__ __launch_bounds__(256) void vmt_kernel() {
    int id = blockIdx.x;
    if (id < 256) {
        int row0 = (id >> 2) * 256;       // token tile
        int col0 = (id & 3) * 128;        // u tile
        gemm_mma<2>(row0, col0, g_xh, g_xl, g_wvth, g_wvtl, DD, DD, DD, 1.0f,
                    nullptr, 0, g_vth, g_vtl, SS);
    } else {
        int id2 = id - 256;
        int row0 = (id2 >> 2) * 256;
        int col0 = (id2 & 3) * 128;
        gemm_mma<1>(row0, col0, g_wkh, g_wkl, g_wqh, g_wql, UU, UU, UU, SCALE,
                    nullptr, 0, g_mth, g_mtl, DD);
    }
}

__global__ __launch_bounds__(256) void p_kernel() {
    // P = x @ Mt^T  -> [B*S][D] split
    gemm_mma<1>(blockIdx.y * 256, blockIdx.x * 128,
                g_xh, g_xl, g_mth, g_mtl, DD, DD, DD, 1.0f,
                nullptr, 0, g_ph, g_pl, DD);
}

__global__ __launch_bounds__(256) void scores_kernel(float* __restrict__ attn) {
    const size_t zo = (size_t)blockIdx.z * SS * DD;
    gemm_mma<0>(blockIdx.y * 256, blockIdx.x * 128,
                g_ph + zo, g_pl + zo, g_xh + zo, g_xl + zo, DD, DD, DD, 1.0f,
                attn + (size_t)blockIdx.z * SS * SS, SS, nullptr, nullptr, 0);
}

__global__ __launch_bounds__(256) void context_kernel(float* __restrict__ ctx) {
    const size_t z = blockIdx.z;
    gemm_mma<0>(blockIdx.y * 256, blockIdx.x * 128,
                g_ah + z * (size_t)SS * SS, g_al + z * (size_t)SS * SS,
                g_vth + z * (size_t)UU * SS, g_vtl + z * (size_t)UU * SS,
                SS, SS, SS, 1.0f,
                ctx + z * (size_t)SS * UU, UU, nullptr, nullptr, 0);
}

// ---------------------------------------------------------------------------
// Elementwise kernels
// ---------------------------------------------------------------------------
__global__ __launch_bounds__(256) void split_x_kernel(const float* __restrict__ in) {
    int i = blockIdx.x * 256 + threadIdx.x;     // float4 granules, NX/4 total
    float4 v = reinterpret_cast<const float4*>(in)[i];
    __nv_bfloat16 h0 = __float2bfloat16(v.x), h1 = __float2bfloat16(v.y);
    __nv_bfloat16 h2 = __float2bfloat16(v.z), h3 = __float2bfloat16(v.w);
    uint2 hp, lp;
    hp.x = pack_bf2(h0, h1); hp.y = pack_bf2(h2, h3);
    lp.x = pack_bf2(__float2bfloat16(v.x - __bfloat162float(h0)),
                    __float2bfloat16(v.y - __bfloat162float(h1)));
    lp.y = pack_bf2(__float2bfloat16(v.z - __bfloat162float(h2)),
                    __float2bfloat16(v.w - __bfloat162float(h3)));
    reinterpret_cast<uint2*>(g_xh)[i] = hp;
    reinterpret_cast<uint2*>(g_xl)[i] = lp;
}

__global__ __launch_bounds__(256) void splitW_kernel(const float* __restrict__ wq,
                                                     const float* __restrict__ wk) {
    const float* src = (blockIdx.y == 0) ? wq : wk;
    __nv_bfloat16* oh = (blockIdx.y == 0) ? g_wqh : g_wkh;
    __nv_bfloat16* ol = (blockIdx.y == 0) ? g_wql : g_wkl;
    int i = blockIdx.x * 256 + threadIdx.x;     // NW/4 granules
    float4 v = reinterpret_cast<const float4*>(src)[i];
    __nv_bfloat16 h0 = __float2bfloat16(v.x), h1 = __float2bfloat16(v.y);
    __nv_bfloat16 h2 = __float2bfloat16(v.z), h3 = __float2bfloat16(v.w);
    uint2 hp, lp;
    hp.x = pack_bf2(h0, h1); hp.y = pack_bf2(h2, h3);
    lp.x = pack_bf2(__float2bfloat16(v.x - __bfloat162float(h0)),
                    __float2bfloat16(v.y - __bfloat162float(h1)));
    lp.y = pack_bf2(__float2bfloat16(v.z - __bfloat162float(h2)),
                    __float2bfloat16(v.w - __bfloat162float(h3)));
    reinterpret_cast<uint2*>(oh)[i] = hp;
    reinterpret_cast<uint2*>(ol)[i] = lp;
}

__global__ void wsplitT_kernel(const float* __restrict__ wv) {
    __shared__ float t[32][33];
    const int u0 = blockIdx.x * 32, d0 = blockIdx.y * 32;
    const int tx = threadIdx.x, ty = threadIdx.y;
#pragma unroll
    for (int p = 0; p < 4; p++)
        t[ty + p * 8][tx] = wv[(size_t)(d0 + ty + p * 8) * UU + u0 + tx];
    __syncthreads();
#pragma unroll
    for (int p = 0; p < 4; p++) {
        float v = t[tx][ty + p * 8];
        __nv_bfloat16 h = __float2bfloat16(v);
        size_t idx = (size_t)(u0 + ty + p * 8) * DD + d0 + tx;
        g_wvth[idx] = h;
        g_wvtl[idx] = __float2bfloat16(v - __bfloat162float(h));
    }
}

__device__ __forceinline__ float warp_max(float v) {
#pragma unroll
    for (int o = 16; o > 0; o >>= 1) v = fmaxf(v, __shfl_xor_sync(0xffffffffu, v, o));
    return v;
}
__device__ __forceinline__ float warp_sum(float v) {
#pragma unroll
    for (int o = 16; o > 0; o >>= 1) v += __shfl_xor_sync(0xffffffffu, v, o);
    return v;
}

__global__ __launch_bounds__(256) void softmax_split_kernel(float* __restrict__ attn) {
    const size_t rowbase = (size_t)blockIdx.x * SS;
    float* p = attn + rowbase;
    const int tid = threadIdx.x;
    __shared__ float red[8];

    float v[8];
#pragma unroll
    for (int j = 0; j < 8; j++) v[j] = p[tid + j * 256];

    float m = v[0];
#pragma unroll
    for (int j = 1; j < 8; j++) m = fmaxf(m, v[j]);
    m = warp_max(m);
    if ((tid & 31) == 0) red[tid >> 5] = m;
    __syncthreads();
    if (tid < 32) {
        float t = (tid < 8) ? red[tid] : -INFINITY;
        t = warp_max(t);
        if (tid == 0) red[0] = t;
    }
    __syncthreads();
    m = red[0];

    float s = 0.0f;
#pragma unroll
    for (int j = 0; j < 8; j++) { v[j] = __expf(v[j] - m); s += v[j]; }
    s = warp_sum(s);
    __syncthreads();
    if ((tid & 31) == 0) red[tid >> 5] = s;
    __syncthreads();
    if (tid < 32) {
        float t = (tid < 8) ? red[tid] : 0.0f;
        t = warp_sum(t);
        if (tid == 0) red[0] = t;
    }
    __syncthreads();
    const float inv = 1.0f / red[0];

#pragma unroll
    for (int j = 0; j < 8; j++) {
        float r = v[j] * inv;
        int col = tid + j * 256;
        p[col] = r;
        __nv_bfloat16 h = __float2bfloat16(r);
        g_ah[rowbase + col] = h;
        g_al[rowbase + col] = __float2bfloat16(r - __bfloat162float(h));
    }
}

// ---------------------------------------------------------------------------
extern "C" void kernel_launch(void* const* d_in, const int* in_sizes, int n_in,
                              void* d_out, int out_size) {
    const float* x  = (const float*)d_in[0];   // [B,S,D]
    const float* wq = (const float*)d_in[1];   // [D,U]
    const float* wk = (const float*)d_in[2];
    const float* wv = (const float*)d_in[3];

    float* out  = (float*)d_out;
    float* ctx  = out;                         // [B,S,U]
    float* attn = out + NX;                    // [B,S,S]

    cudaFuncSetAttribute(vmt_kernel,     cudaFuncAttributeMaxDynamicSharedMemorySize, SMEM_DYN);
    cudaFuncSetAttribute(p_kernel,       cudaFuncAttributeMaxDynamicSharedMemorySize, SMEM_DYN);
    cudaFuncSetAttribute(scores_kernel,  cudaFuncAttributeMaxDynamicSharedMemorySize, SMEM_DYN);
    cudaFuncSetAttribute(context_kernel, cudaFuncAttributeMaxDynamicSharedMemorySize, SMEM_DYN);

    // 1. splits: x, Wq, Wk (plain), Wv (transposed)
    split_x_kernel<<<(int)(NX / 4 / 256), 256>>>(x);
    splitW_kernel<<<dim3((int)(NW / 4 / 256), 2), 256>>>(wq, wk);
    wsplitT_kernel<<<dim3(UU / 32, DD / 32), dim3(32, 8)>>>(wv);

    // 2. V^T = (x @ Wv)^T (256 blocks) and Mt = scale * Wk @ Wq^T (8 blocks)
    vmt_kernel<<<dim3(264), 256, SMEM_DYN>>>();

    // 3. P = x @ Mt^T  [16384x512]
    p_kernel<<<dim3(4, 64), 256, SMEM_DYN>>>();

    // 4. scores = P @ x^T per batch (scale already folded into Mt)
    scores_kernel<<<dim3(16, 8, BB), 256, SMEM_DYN>>>(attn);

    // 5. softmax + bf16 hi/lo split of attn
    softmax_split_kernel<<<dim3(BB * SS), 256>>>(attn);

    // 6. context = attn @ V per batch
    context_kernel<<<dim3(4, 8, BB), 256, SMEM_DYN>>>(ctx);
}

// round 10
// speedup vs baseline: 1.1873x; 1.1873x over previous
#include <cuda_runtime.h>
#include <cuda_bf16.h>
#include <cstdint>
#include <math.h>

// Problem constants
#define BB 8
#define SS 2048
#define DD 512
#define UU 512

#define NX ((size_t)BB * SS * DD)      // 8388608
#define NW ((size_t)DD * UU)           // 262144
#define NA ((size_t)BB * SS * SS)      // 33554432

#define SCALE 0.04419417382415922f    // 1/sqrt(512)

// ---------------------------------------------------------------------------
// Device-global scratch (no allocations allowed)
// ---------------------------------------------------------------------------
__device__ __align__(128) __nv_bfloat16 g_xh[NX],  g_xl[NX];     // x splits [B*S][D]
__device__ __align__(128) __nv_bfloat16 g_wqh[NW], g_wql[NW];    // Wq splits [D][U]
__device__ __align__(128) __nv_bfloat16 g_wkh[NW], g_wkl[NW];    // Wk splits [D][U]
__device__ __align__(128) __nv_bfloat16 g_wvth[NW], g_wvtl[NW];  // Wv^T splits [U][D]
__device__ __align__(128) __nv_bfloat16 g_mth[NW], g_mtl[NW];    // Mt = scale*Wk Wq^T [D][D]
__device__ __align__(128) __nv_bfloat16 g_ph[NX],  g_pl[NX];     // P = x Mt^T [B*S][D]
__device__ __align__(128) __nv_bfloat16 g_vth[NX], g_vtl[NX];    // V^T splits [B][U][S]
__device__ __align__(128) __nv_bfloat16 g_ah[NA],  g_al[NA];     // attn splits [B][S][S]

// ---------------------------------------------------------------------------
// Helpers
// ---------------------------------------------------------------------------
__device__ __forceinline__ uint32_t smem_u32(const void* p) {
    uint32_t a;
    asm("{ .reg .u64 t; cvta.to.shared.u64 t, %1; cvt.u32.u64 %0, t; }" : "=r"(a) : "l"(p));
    return a;
}
__device__ __forceinline__ uint32_t pack_bf2(__nv_bfloat16 a, __nv_bfloat16 b) {
    return (uint32_t)__bfloat16_as_ushort(a) | ((uint32_t)__bfloat16_as_ushort(b) << 16);
}

#define LDSM4(r0, r1, r2, r3, addr) \
    asm volatile("ldmatrix.sync.aligned.m8n8.x4.shared.b16 {%0,%1,%2,%3}, [%4];" \
        : "=r"(r0), "=r"(r1), "=r"(r2), "=r"(r3) : "r"(addr))

#define MMA16816(d, a, b) \
    asm volatile("mma.sync.aligned.m16n8k16.row.col.f32.bf16.bf16.f32 " \
        "{%0,%1,%2,%3}, {%4,%5,%6,%7}, {%8,%9}, {%0,%1,%2,%3};" \
        : "+f"((d)[0]), "+f"((d)[1]), "+f"((d)[2]), "+f"((d)[3]) \
        : "r"((a)[0]), "r"((a)[1]), "r"((a)[2]), "r"((a)[3]), \
          "r"((b)[0]), "r"((b)[1]))

// ---------------------------------------------------------------------------
// bf16x3 mma GEMM: 128x128 CTA tile, BK=32, 256 threads (8 warps, 2x4 grid,
// 64x32 warp tile), 3-stage cp.async pipeline, 2 CTAs/SM.
// Smem: 64-byte rows with XOR swizzle phys_chunk = c ^ ((r>>1)&3).
//   - cp.async stores: 4 lanes per row cover the 4 chunks bijectively.
//   - ldmatrix reads: even rows (bank base 0) get 4 distinct chunks via
//     (r>>1)&3 = 0..3, odd rows likewise -> conflict-free.
// ALL operands K-major: A MxK (hi/lo), B NxK (hi/lo). C = A * B^T.
// MODE 0: fp32 store.  MODE 1: alpha-scaled bf16 hi/lo split store.
// MODE 2: bf16 hi/lo split TRANSPOSED store (per-batch V^T layout).
// ---------------------------------------------------------------------------
#define ARR_B 8192                      // 128 rows * 64 bytes per array
#define STG_B 32768                     // 4 arrays per stage
#define SMEM_DYN (3 * STG_B)            // 98304 bytes

__device__ __forceinline__ void stage_arr(uint32_t sdst, const __nv_bfloat16* __restrict__ src,
                                          int r0, int k0, int ld, int tid) {
#pragma unroll
    for (int j = 0; j < 2; j++) {
        int idx = tid + j * 256;                  // 512 chunks of 16B
        int r = idx >> 2, c = idx & 3;
        int phys = c ^ ((r >> 1) & 3);
        uint32_t dst = sdst + (uint32_t)(r * 64 + phys * 16);
        const void* gp = (const void*)(src + (size_t)(r0 + r) * ld + k0 + c * 8);
        asm volatile("cp.async.cg.shared.global [%0], [%1], 16;" :: "r"(dst), "l"(gp));
    }
}

__device__ __forceinline__ void stage_all(uint32_t sb,
                                          const __nv_bfloat16* Ah, const __nv_bfloat16* Al,
                                          const __nv_bfloat16* Bh, const __nv_bfloat16* Bl,
                                          int row0, int col0, int k0, int lda, int ldb, int tid) {
    stage_arr(sb + 0 * ARR_B, Ah, row0, k0, lda, tid);
    stage_arr(sb + 1 * ARR_B, Al, row0, k0, lda, tid);
    stage_arr(sb + 2 * ARR_B, Bh, col0, k0, ldb, tid);
    stage_arr(sb + 3 * ARR_B, Bl, col0, k0, ldb, tid);
    asm volatile("cp.async.commit_group;" ::: "memory");
}

template <int MODE>
__device__ __forceinline__ void gemm_mma(int row0, int col0,
                                         const __nv_bfloat16* __restrict__ Ah,
                                         const __nv_bfloat16* __restrict__ Al,
                                         const __nv_bfloat16* __restrict__ Bh,
                                         const __nv_bfloat16* __restrict__ Bl,
                                         int K, int lda, int ldb, float alpha,
                                         float* __restrict__ Cf, int ldc,
                                         __nv_bfloat16* __restrict__ Oh,
                                         __nv_bfloat16* __restrict__ Ol, int ldo) {
    extern __shared__ __nv_bfloat16 smem[];

    const int tid  = threadIdx.x;
    const int warp = tid >> 5;
    const int lane = tid & 31;
    const int wm = (warp >> 2) * 64;     // warp row: 0 / 64
    const int wn = (warp & 3) * 32;      // warp col: 0..96

    const uint32_t sbase = smem_u32(smem);

    // Per-lane ldmatrix row/swizzle precompute.
    // A x4: lanes 0-7 (m0-7,klo) 8-15 (m8-15,klo) 16-23 (m0-7,khi) 24-31 (m8-15,khi)
    const int aRow = wm + ((lane >> 3) & 1) * 8 + (lane & 7);
    const uint32_t aOff = (uint32_t)(aRow * 64);
    const uint32_t aS   = (uint32_t)((aRow >> 1) & 3);
    const uint32_t aK   = (uint32_t)(lane >> 4);            // 16B chunk within k16
    // B x4: lanes 0-7 (n0-7,klo) 8-15 (n0-7,khi) 16-23 (n8-15,klo) 24-31 (n8-15,khi)
    const int bRow = wn + ((lane >> 4) & 1) * 8 + (lane & 7);
    const uint32_t bOff = (uint32_t)(bRow * 64);
    const uint32_t bS   = (uint32_t)((bRow >> 1) & 3);
    const uint32_t bK   = (uint32_t)((lane >> 3) & 1);

    float acc[4][4][4];                  // [i m16][j n8][4]
#pragma unroll
    for (int i = 0; i < 4; i++)
#pragma unroll
        for (int j = 0; j < 4; j++)
#pragma unroll
            for (int e = 0; e < 4; e++) acc[i][j][e] = 0.0f;

    const int niter = K >> 5;

    // prologue: stage iters 0,1
    stage_all(sbase, Ah, Al, Bh, Bl, row0, col0, 0, lda, ldb, tid);
    stage_all(sbase + STG_B, Ah, Al, Bh, Bl, row0, col0, 32, lda, ldb, tid);

    int buf = 0;
    for (int it = 0; it < niter; it++) {
        if (it + 1 < niter) {
            asm volatile("cp.async.wait_group 1;" ::: "memory");
        } else {
            asm volatile("cp.async.wait_group 0;" ::: "memory");
        }
        __syncthreads();
        if (it + 2 < niter) {
            int nb = buf + 2; if (nb >= 3) nb -= 3;
            stage_all(sbase + (uint32_t)(nb * STG_B), Ah, Al, Bh, Bl,
                      row0, col0, (it + 2) << 5, lda, ldb, tid);
        }

        const uint32_t base = sbase + (uint32_t)(buf * STG_B);
        const uint32_t pAh = base + 0 * ARR_B + aOff;
        const uint32_t pAl = base + 1 * ARR_B + aOff;
        const uint32_t pBh = base + 2 * ARR_B + bOff;
        const uint32_t pBl = base + 3 * ARR_B + bOff;

#pragma unroll
        for (int ks = 0; ks < 2; ks++) {
            const uint32_t koA = (((ks * 2 + aK) ^ aS) << 4);
            const uint32_t koB = (((ks * 2 + bK) ^ bS) << 4);
            uint32_t ah[4][4], al[4][4];         // [i][reg]
            uint32_t bh[4][2], bl[4][2];         // [j][reg]
#pragma unroll
            for (int jp = 0; jp < 2; jp++) {     // n16 groups: rows +0, +16
                LDSM4(bh[2 * jp][0], bh[2 * jp][1], bh[2 * jp + 1][0], bh[2 * jp + 1][1],
                      pBh + jp * 1024 + koB);
                LDSM4(bl[2 * jp][0], bl[2 * jp][1], bl[2 * jp + 1][0], bl[2 * jp + 1][1],
                      pBl + jp * 1024 + koB);
            }
#pragma unroll
            for (int i = 0; i < 4; i++) {        // m16 groups: rows +16 each
                LDSM4(ah[i][0], ah[i][1], ah[i][2], ah[i][3], pAh + i * 1024 + koA);
                LDSM4(al[i][0], al[i][1], al[i][2], al[i][3], pAl + i * 1024 + koA);
            }
            // term-major MMA issue: no consecutive same-accumulator ops
#pragma unroll
            for (int i = 0; i < 4; i++)
#pragma unroll
                for (int j = 0; j < 4; j++) MMA16816(acc[i][j], ah[i], bh[j]);
#pragma unroll
            for (int i = 0; i < 4; i++)
#pragma unroll
                for (int j = 0; j < 4; j++) MMA16816(acc[i][j], ah[i], bl[j]);
#pragma unroll
            for (int i = 0; i < 4; i++)
#pragma unroll
                for (int j = 0; j < 4; j++) MMA16816(acc[i][j], al[i], bh[j]);
        }
        buf++; if (buf == 3) buf = 0;
    }

    // ------------------------- epilogue -------------------------
    // acc frag layout: c0:(m=lane/4, n=2(lane%4)) c1:(m,n+1) c2:(m+8,n) c3:(m+8,n+1)
    const int er = lane >> 2;
    const int ec = (lane & 3) * 2;

    if constexpr (MODE == 0) {
#pragma unroll
        for (int i = 0; i < 4; i++)
#pragma unroll
            for (int j = 0; j < 4; j++) {
                size_t r = (size_t)(row0 + wm + i * 16 + er);
                int c = col0 + wn + j * 8 + ec;
                *reinterpret_cast<float2*>(&Cf[r * ldc + c]) =
                    make_float2(acc[i][j][0], acc[i][j][1]);
                *reinterpret_cast<float2*>(&Cf[(r + 8) * ldc + c]) =
                    make_float2(acc[i][j][2], acc[i][j][3]);
            }
    } else {
        __syncthreads();   // all warps done reading pipeline stages before smem reuse
        float* ew = (float*)(smem + warp * 768);   // 16x24 floats = 1536 B per warp
        if constexpr (MODE == 1) {
#pragma unroll
            for (int i = 0; i < 4; i++)
#pragma unroll
                for (int jp = 0; jp < 2; jp++) {
                    int j0 = 2 * jp, j1 = 2 * jp + 1;
                    ew[er * 24 + ec]            = acc[i][j0][0];
                    ew[er * 24 + ec + 1]        = acc[i][j0][1];
                    ew[(er + 8) * 24 + ec]      = acc[i][j0][2];
                    ew[(er + 8) * 24 + ec + 1]  = acc[i][j0][3];
                    ew[er * 24 + 8 + ec]        = acc[i][j1][0];
                    ew[er * 24 + 8 + ec + 1]    = acc[i][j1][1];
                    ew[(er + 8) * 24 + 8 + ec]     = acc[i][j1][2];
                    ew[(er + 8) * 24 + 8 + ec + 1] = acc[i][j1][3];
                    __syncwarp();
                    int r = lane >> 1, cb = (lane & 1) * 8;
                    float v[8];
#pragma unroll
                    for (int e = 0; e < 8; e++) v[e] = ew[r * 24 + cb + e] * alpha;
                    uint4 hp, lp;
                    __nv_bfloat16 h[8];
#pragma unroll
                    for (int e = 0; e < 8; e++) h[e] = __float2bfloat16(v[e]);
                    hp.x = pack_bf2(h[0], h[1]); hp.y = pack_bf2(h[2], h[3]);
                    hp.z = pack_bf2(h[4], h[5]); hp.w = pack_bf2(h[6], h[7]);
                    __nv_bfloat16 l[8];
#pragma unroll
                    for (int e = 0; e < 8; e++) l[e] = __float2bfloat16(v[e] - __bfloat162float(h[e]));
                    lp.x = pack_bf2(l[0], l[1]); lp.y = pack_bf2(l[2], l[3]);
                    lp.z = pack_bf2(l[4], l[5]); lp.w = pack_bf2(l[6], l[7]);
                    size_t idx = (size_t)(row0 + wm + i * 16 + r) * ldo + col0 + wn + jp * 16 + cb;
                    *reinterpret_cast<uint4*>(&Oh[idx]) = hp;
                    *reinterpret_cast<uint4*>(&Ol[idx]) = lp;
                    __syncwarp();
                }
        } else {
            // MODE 2: transposed split (V^T), row0 indexes tokens [B*S]
            const int b  = row0 >> 11;               // SS == 2048
            __nv_bfloat16* ohb = Oh + (size_t)b * UU * SS;
            __nv_bfloat16* olb = Ol + (size_t)b * UU * SS;
#pragma unroll
            for (int i = 0; i < 4; i++)
#pragma unroll
                for (int jp = 0; jp < 2; jp++) {
                    int j0 = 2 * jp, j1 = 2 * jp + 1;
                    ew[er * 24 + ec]            = acc[i][j0][0];
                    ew[er * 24 + ec + 1]        = acc[i][j0][1];
                    ew[(er + 8) * 24 + ec]      = acc[i][j0][2];
                    ew[(er + 8) * 24 + ec + 1]  = acc[i][j0][3];
                    ew[er * 24 + 8 + ec]        = acc[i][j1][0];
                    ew[er * 24 + 8 + ec + 1]    = acc[i][j1][1];
                    ew[(er + 8) * 24 + 8 + ec]     = acc[i][j1][2];
                    ew[(er + 8) * 24 + 8 + ec + 1] = acc[i][j1][3];
                    __syncwarp();
                    if (lane < 16) {
                        int u = lane;
                        float v[16];
#pragma unroll
                        for (int r = 0; r < 16; r++) v[r] = ew[r * 24 + u];
                        uint32_t hw[8], lw[8];
#pragma unroll
                        for (int e = 0; e < 8; e++) {
                            __nv_bfloat16 ha = __float2bfloat16(v[2 * e]);
                            __nv_bfloat16 hb = __float2bfloat16(v[2 * e + 1]);
                            hw[e] = pack_bf2(ha, hb);
                            lw[e] = pack_bf2(__float2bfloat16(v[2 * e] - __bfloat162float(ha)),
                                             __float2bfloat16(v[2 * e + 1] - __bfloat162float(hb)));
                        }
                        int s0 = (row0 & 2047) + wm + i * 16;
                        size_t idx = (size_t)(col0 + wn + jp * 16 + u) * SS + s0;
                        uint4 h0, h1, l0, l1;
                        h0.x = hw[0]; h0.y = hw[1]; h0.z = hw[2]; h0.w = hw[3];
                        h1.x = hw[4]; h1.y = hw[5]; h1.z = hw[6]; h1.w = hw[7];
                        l0.x = lw[0]; l0.y = lw[1]; l0.z = lw[2]; l0.w = lw[3];
                        l1.x = lw[4]; l1.y = lw[5]; l1.z = lw[6]; l1.w = lw[7];
                        *reinterpret_cast<uint4*>(&ohb[idx])     = h0;
                        *reinterpret_cast<uint4*>(&ohb[idx + 8]) = h1;
                        *reinterpret_cast<uint4*>(&olb[idx])     = l0;
                        *reinterpret_cast<uint4*>(&olb[idx + 8]) = l1;
                    }
                    __syncwarp();
                }
        }
    }
}

// ---------------------------------------------------------------------------
// GEMM kernel wrappers (2 CTAs/SM)
// ---------------------------------------------------------------------------

// Combined V^T projection (blocks 0..511) + Mt (blocks 512..527).
__global__ __launch_bounds__(256, 2) void vmt_kernel() {
    int id = blockIdx.x;
    if (id < 512) {
        int row0 = (id >> 2) * 128;       // token tile
        int col0 = (id & 3) * 128;        // u tile
        gemm_mma<2>(row0, col0, g_xh, g_xl, g_wvth, g_wvtl, DD, DD, DD, 1.0f,
                    nullptr, 0, g_vth, g_vtl, SS);
    } else {
        int id2 = id - 512;
        int row0 = (id2 >> 2) * 128;
        int col0 = (id2 & 3) * 128;
        gemm_mma<1>(row0, col0, g_wkh, g_wkl, g_wqh, g_wql, UU, UU, UU, SCALE,
                    nullptr, 0, g_mth, g_mtl, DD);
    }
}

__global__ __launch_bounds__(256, 2) void p_kernel() {
    // P = x @ Mt^T  -> [B*S][D] split
    gemm_mma<1>(blockIdx.y * 128, blockIdx.x * 128,
                g_xh, g_xl, g_mth, g_mtl, DD, DD, DD, 1.0f,
                nullptr, 0, g_ph, g_pl, DD);
}

__global__ __launch_bounds__(256, 2) void scores_kernel(float* __restrict__ attn) {
    const size_t zo = (size_t)blockIdx.z * SS * DD;
    gemm_mma<0>(blockIdx.y * 128, blockIdx.x * 128,
                g_ph + zo, g_pl + zo, g_xh + zo, g_xl + zo, DD, DD, DD, 1.0f,
                attn + (size_t)blockIdx.z * SS * SS, SS, nullptr, nullptr, 0);
}

__global__ __launch_bounds__(256, 2) void context_kernel(float* __restrict__ ctx) {
    const size_t z = blockIdx.z;
    gemm_mma<0>(blockIdx.y * 128, blockIdx.x * 128,
                g_ah + z * (size_t)SS * SS, g_al + z * (size_t)SS * SS,
                g_vth + z * (size_t)UU * SS, g_vtl + z * (size_t)UU * SS,
                SS, SS, SS, 1.0f,
                ctx + z * (size_t)SS * UU, UU, nullptr, nullptr, 0);
}

// ---------------------------------------------------------------------------
// Elementwise kernels
// ---------------------------------------------------------------------------
__global__ __launch_bounds__(256) void split_x_kernel(const float* __restrict__ in) {
    int i = blockIdx.x * 256 + threadIdx.x;     // float4 granules, NX/4 total
    float4 v = reinterpret_cast<const float4*>(in)[i];
    __nv_bfloat16 h0 = __float2bfloat16(v.x), h1 = __float2bfloat16(v.y);
    __nv_bfloat16 h2 = __float2bfloat16(v.z), h3 = __float2bfloat16(v.w);
    uint2 hp, lp;
    hp.x = pack_bf2(h0, h1); hp.y = pack_bf2(h2, h3);
    lp.x = pack_bf2(__float2bfloat16(v.x - __bfloat162float(h0)),
                    __float2bfloat16(v.y - __bfloat162float(h1)));
    lp.y = pack_bf2(__float2bfloat16(v.z - __bfloat162float(h2)),
                    __float2bfloat16(v.w - __bfloat162float(h3)));
    reinterpret_cast<uint2*>(g_xh)[i] = hp;
    reinterpret_cast<uint2*>(g_xl)[i] = lp;
}

__global__ __launch_bounds__(256) void splitW_kernel(const float* __restrict__ wq,
                                                     const float* __restrict__ wk) {
    const float* src = (blockIdx.y == 0) ? wq : wk;
    __nv_bfloat16* oh = (blockIdx.y == 0) ? g_wqh : g_wkh;
    __nv_bfloat16* ol = (blockIdx.y == 0) ? g_wql : g_wkl;
    int i = blockIdx.x * 256 + threadIdx.x;     // NW/4 granules
    float4 v = reinterpret_cast<const float4*>(src)[i];
    __nv_bfloat16 h0 = __float2bfloat16(v.x), h1 = __float2bfloat16(v.y);
    __nv_bfloat16 h2 = __float2bfloat16(v.z), h3 = __float2bfloat16(v.w);
    uint2 hp, lp;
    hp.x = pack_bf2(h0, h1); hp.y = pack_bf2(h2, h3);
    lp.x = pack_bf2(__float2bfloat16(v.x - __bfloat162float(h0)),
                    __float2bfloat16(v.y - __bfloat162float(h1)));
    lp.y = pack_bf2(__float2bfloat16(v.z - __bfloat162float(h2)),
                    __float2bfloat16(v.w - __bfloat162float(h3)));
    reinterpret_cast<uint2*>(oh)[i] = hp;
    reinterpret_cast<uint2*>(ol)[i] = lp;
}

__global__ void wsplitT_kernel(const float* __restrict__ wv) {
    __shared__ float t[32][33];
    const int u0 = blockIdx.x * 32, d0 = blockIdx.y * 32;
    const int tx = threadIdx.x, ty = threadIdx.y;
#pragma unroll
    for (int p = 0; p < 4; p++)
        t[ty + p * 8][tx] = wv[(size_t)(d0 + ty + p * 8) * UU + u0 + tx];
    __syncthreads();
#pragma unroll
    for (int p = 0; p < 4; p++) {
        float v = t[tx][ty + p * 8];
        __nv_bfloat16 h = __float2bfloat16(v);
        size_t idx = (size_t)(u0 + ty + p * 8) * DD + d0 + tx;
        g_wvth[idx] = h;
        g_wvtl[idx] = __float2bfloat16(v - __bfloat162float(h));
    }
}

__device__ __forceinline__ float warp_max(float v) {
#pragma unroll
    for (int o = 16; o > 0; o >>= 1) v = fmaxf(v, __shfl_xor_sync(0xffffffffu, v, o));
    return v;
}
__device__ __forceinline__ float warp_sum(float v) {
#pragma unroll
    for (int o = 16; o > 0; o >>= 1) v += __shfl_xor_sync(0xffffffffu, v, o);
    return v;
}

__global__ __launch_bounds__(256) void softmax_split_kernel(float* __restrict__ attn) {
    const size_t rowbase = (size_t)blockIdx.x * SS;
    float* p = attn + rowbase;
    const int tid = threadIdx.x;
    __shared__ float red[8];

    float v[8];
#pragma unroll
    for (int j = 0; j < 8; j++) v[j] = p[tid + j * 256];

    float m = v[0];
#pragma unroll
    for (int j = 1; j < 8; j++) m = fmaxf(m, v[j]);
    m = warp_max(m);
    if ((tid & 31) == 0) red[tid >> 5] = m;
    __syncthreads();
    if (tid < 32) {
        float t = (tid < 8) ? red[tid] : -INFINITY;
        t = warp_max(t);
        if (tid == 0) red[0] = t;
    }
    __syncthreads();
    m = red[0];

    float s = 0.0f;
#pragma unroll
    for (int j = 0; j < 8; j++) { v[j] = __expf(v[j] - m); s += v[j]; }
    s = warp_sum(s);
    __syncthreads();
    if ((tid & 31) == 0) red[tid >> 5] = s;
    __syncthreads();
    if (tid < 32) {
        float t = (tid < 8) ? red[tid] : 0.0f;
        t = warp_sum(t);
        if (tid == 0) red[0] = t;
    }
    __syncthreads();
    const float inv = 1.0f / red[0];

#pragma unroll
    for (int j = 0; j < 8; j++) {
        float r = v[j] * inv;
        int col = tid + j * 256;
        p[col] = r;
        __nv_bfloat16 h = __float2bfloat16(r);
        g_ah[rowbase + col] = h;
        g_al[rowbase + col] = __float2bfloat16(r - __bfloat162float(h));
    }
}

// ---------------------------------------------------------------------------
extern "C" void kernel_launch(void* const* d_in, const int* in_sizes, int n_in,
                              void* d_out, int out_size) {
    const float* x  = (const float*)d_in[0];   // [B,S,D]
    const float* wq = (const float*)d_in[1];   // [D,U]
    const float* wk = (const float*)d_in[2];
    const float* wv = (const float*)d_in[3];

    float* out  = (float*)d_out;
    float* ctx  = out;                         // [B,S,U]
    float* attn = out + NX;                    // [B,S,S]

    cudaFuncSetAttribute(vmt_kernel,     cudaFuncAttributeMaxDynamicSharedMemorySize, SMEM_DYN);
    cudaFuncSetAttribute(p_kernel,       cudaFuncAttributeMaxDynamicSharedMemorySize, SMEM_DYN);
    cudaFuncSetAttribute(scores_kernel,  cudaFuncAttributeMaxDynamicSharedMemorySize, SMEM_DYN);
    cudaFuncSetAttribute(context_kernel, cudaFuncAttributeMaxDynamicSharedMemorySize, SMEM_DYN);

    // 1. splits: x, Wq, Wk (plain), Wv (transposed)
    split_x_kernel<<<(int)(NX / 4 / 256), 256>>>(x);
    splitW_kernel<<<dim3((int)(NW / 4 / 256), 2), 256>>>(wq, wk);
    wsplitT_kernel<<<dim3(UU / 32, DD / 32), dim3(32, 8)>>>(wv);

    // 2. V^T = (x @ Wv)^T  and  Mt = scale * Wk @ Wq^T  (one launch)
    vmt_kernel<<<dim3(528), 256, SMEM_DYN>>>();

    // 3. P = x @ Mt^T  [16384x512]
    p_kernel<<<dim3(4, 128), 256, SMEM_DYN>>>();

    // 4. scores = P @ x^T per batch (scale already folded into Mt)
    scores_kernel<<<dim3(16, 16, BB), 256, SMEM_DYN>>>(attn);

    // 5. softmax + bf16 hi/lo split of attn
    softmax_split_kernel<<<dim3(BB * SS), 256>>>(attn);

    // 6. context = attn @ V per batch
    context_kernel<<<dim3(4, 16, BB), 256, SMEM_DYN>>>(ctx);
}

// round 11
// speedup vs baseline: 1.1874x; 1.0001x over previous
#include <cuda_runtime.h>
#include <cuda_bf16.h>
#include <cstdint>
#include <math.h>

// Problem constants
#define BB 8
#define SS 2048
#define DD 512
#define UU 512

#define NX ((size_t)BB * SS * DD)      // 8388608
#define NW ((size_t)DD * UU)           // 262144
#define NA ((size_t)BB * SS * SS)      // 33554432

#define SCALE 0.04419417382415922f    // 1/sqrt(512)

// ---------------------------------------------------------------------------
// Device-global scratch (no allocations allowed)
// ---------------------------------------------------------------------------
__device__ __align__(128) __nv_bfloat16 g_xh[NX],  g_xl[NX];     // x splits [B*S][D]
__device__ __align__(128) __nv_bfloat16 g_wqh[NW], g_wql[NW];    // Wq splits [D][U]
__device__ __align__(128) __nv_bfloat16 g_wkh[NW], g_wkl[NW];    // Wk splits [D][U]
__device__ __align__(128) __nv_bfloat16 g_wvth[NW], g_wvtl[NW];  // Wv^T splits [U][D]
__device__ __align__(128) __nv_bfloat16 g_mth[NW], g_mtl[NW];    // Mt = scale*Wk Wq^T [D][D]
__device__ __align__(128) __nv_bfloat16 g_ph[NX],  g_pl[NX];     // P = x Mt^T [B*S][D]
__device__ __align__(128) __nv_bfloat16 g_vth[NX], g_vtl[NX];    // V^T splits [B][U][S]
__device__ __align__(128) __nv_bfloat16 g_ah[NA],  g_al[NA];     // attn splits [B][S][S]

// ---------------------------------------------------------------------------
// Helpers
// ---------------------------------------------------------------------------
__device__ __forceinline__ uint32_t smem_u32(const void* p) {
    uint32_t a;
    asm("{ .reg .u64 t; cvta.to.shared.u64 t, %1; cvt.u32.u64 %0, t; }" : "=r"(a) : "l"(p));
    return a;
}
__device__ __forceinline__ uint32_t pack_bf2(__nv_bfloat16 a, __nv_bfloat16 b) {
    return (uint32_t)__bfloat16_as_ushort(a) | ((uint32_t)__bfloat16_as_ushort(b) << 16);
}

// LDSM stays volatile: it reads pipeline smem; hoisting across __syncthreads
// would read stale data.  MMA is NON-volatile: pure register math, so ptxas
// may interleave it with subsequent LDSM batches (hides the frag-load bubble).
#define LDSM4(r0, r1, r2, r3, addr) \
    asm volatile("ldmatrix.sync.aligned.m8n8.x4.shared.b16 {%0,%1,%2,%3}, [%4];" \
        : "=r"(r0), "=r"(r1), "=r"(r2), "=r"(r3) : "r"(addr))

#define MMA16816(d, a, b) \
    asm("mma.sync.aligned.m16n8k16.row.col.f32.bf16.bf16.f32 " \
        "{%0,%1,%2,%3}, {%4,%5,%6,%7}, {%8,%9}, {%0,%1,%2,%3};" \
        : "+f"((d)[0]), "+f"((d)[1]), "+f"((d)[2]), "+f"((d)[3]) \
        : "r"((a)[0]), "r"((a)[1]), "r"((a)[2]), "r"((a)[3]), \
          "r"((b)[0]), "r"((b)[1]))

// ---------------------------------------------------------------------------
// bf16x3 mma GEMM: 128x128 CTA tile, BK=32, 256 threads (8 warps, 2x4 grid,
// 64x32 warp tile), 3-stage cp.async pipeline, 2 CTAs/SM.
// Smem: 64-byte rows with XOR swizzle phys_chunk = c ^ ((r>>1)&3).
// ALL operands K-major: A MxK (hi/lo), B NxK (hi/lo). C = A * B^T.
// MODE 0: fp32 store.  MODE 1: alpha-scaled bf16 hi/lo split store.
// MODE 2: bf16 hi/lo split TRANSPOSED store (per-batch V^T layout).
// ---------------------------------------------------------------------------
#define ARR_B 8192                      // 128 rows * 64 bytes per array
#define STG_B 32768                     // 4 arrays per stage
#define SMEM_DYN (3 * STG_B)            // 98304 bytes

__device__ __forceinline__ void stage_arr(uint32_t sdst, const __nv_bfloat16* __restrict__ src,
                                          int r0, int k0, int ld, int tid) {
#pragma unroll
    for (int j = 0; j < 2; j++) {
        int idx = tid + j * 256;                  // 512 chunks of 16B
        int r = idx >> 2, c = idx & 3;
        int phys = c ^ ((r >> 1) & 3);
        uint32_t dst = sdst + (uint32_t)(r * 64 + phys * 16);
        const void* gp = (const void*)(src + (size_t)(r0 + r) * ld + k0 + c * 8);
        asm volatile("cp.async.cg.shared.global [%0], [%1], 16;" :: "r"(dst), "l"(gp));
    }
}

__device__ __forceinline__ void stage_all(uint32_t sb,
                                          const __nv_bfloat16* Ah, const __nv_bfloat16* Al,
                                          const __nv_bfloat16* Bh, const __nv_bfloat16* Bl,
                                          int row0, int col0, int k0, int lda, int ldb, int tid) {
    stage_arr(sb + 0 * ARR_B, Ah, row0, k0, lda, tid);
    stage_arr(sb + 1 * ARR_B, Al, row0, k0, lda, tid);
    stage_arr(sb + 2 * ARR_B, Bh, col0, k0, ldb, tid);
    stage_arr(sb + 3 * ARR_B, Bl, col0, k0, ldb, tid);
    asm volatile("cp.async.commit_group;" ::: "memory");
}

template <int MODE>
__device__ __forceinline__ void gemm_mma(int row0, int col0,
                                         const __nv_bfloat16* __restrict__ Ah,
                                         const __nv_bfloat16* __restrict__ Al,
                                         const __nv_bfloat16* __restrict__ Bh,
                                         const __nv_bfloat16* __restrict__ Bl,
                                         int K, int lda, int ldb, float alpha,
                                         float* __restrict__ Cf, int ldc,
                                         __nv_bfloat16* __restrict__ Oh,
                                         __nv_bfloat16* __restrict__ Ol, int ldo) {
    extern __shared__ __nv_bfloat16 smem[];

    const int tid  = threadIdx.x;
    const int warp = tid >> 5;
    const int lane = tid & 31;
    const int wm = (warp >> 2) * 64;     // warp row: 0 / 64
    const int wn = (warp & 3) * 32;      // warp col: 0..96

    const uint32_t sbase = smem_u32(smem);

    // Per-lane ldmatrix row/swizzle precompute.
    const int aRow = wm + ((lane >> 3) & 1) * 8 + (lane & 7);
    const uint32_t aOff = (uint32_t)(aRow * 64);
    const uint32_t aS   = (uint32_t)((aRow >> 1) & 3);
    const uint32_t aK   = (uint32_t)(lane >> 4);            // 16B chunk within k16
    const int bRow = wn + ((lane >> 4) & 1) * 8 + (lane & 7);
    const uint32_t bOff = (uint32_t)(bRow * 64);
    const uint32_t bS   = (uint32_t)((bRow >> 1) & 3);
    const uint32_t bK   = (uint32_t)((lane >> 3) & 1);

    float acc[4][4][4];                  // [i m16][j n8][4]
#pragma unroll
    for (int i = 0; i < 4; i++)
#pragma unroll
        for (int j = 0; j < 4; j++)
#pragma unroll
            for (int e = 0; e < 4; e++) acc[i][j][e] = 0.0f;

    const int niter = K >> 5;

    // prologue: stage iters 0,1
    stage_all(sbase, Ah, Al, Bh, Bl, row0, col0, 0, lda, ldb, tid);
    stage_all(sbase + STG_B, Ah, Al, Bh, Bl, row0, col0, 32, lda, ldb, tid);

    int buf = 0;
    for (int it = 0; it < niter; it++) {
        if (it + 1 < niter) {
            asm volatile("cp.async.wait_group 1;" ::: "memory");
        } else {
            asm volatile("cp.async.wait_group 0;" ::: "memory");
        }
        __syncthreads();
        if (it + 2 < niter) {
            int nb = buf + 2; if (nb >= 3) nb -= 3;
            stage_all(sbase + (uint32_t)(nb * STG_B), Ah, Al, Bh, Bl,
                      row0, col0, (it + 2) << 5, lda, ldb, tid);
        }

        const uint32_t base = sbase + (uint32_t)(buf * STG_B);
        const uint32_t pAh = base + 0 * ARR_B + aOff;
        const uint32_t pAl = base + 1 * ARR_B + aOff;
        const uint32_t pBh = base + 2 * ARR_B + bOff;
        const uint32_t pBl = base + 3 * ARR_B + bOff;

#pragma unroll
        for (int ks = 0; ks < 2; ks++) {
            const uint32_t koA = (((ks * 2 + aK) ^ aS) << 4);
            const uint32_t koB = (((ks * 2 + bK) ^ bS) << 4);
            uint32_t ah[4][4], al[4][4];         // [i][reg]
            uint32_t bh[4][2], bl[4][2];         // [j][reg]
#pragma unroll
            for (int jp = 0; jp < 2; jp++) {     // n16 groups: rows +0, +16
                LDSM4(bh[2 * jp][0], bh[2 * jp][1], bh[2 * jp + 1][0], bh[2 * jp + 1][1],
                      pBh + jp * 1024 + koB);
                LDSM4(bl[2 * jp][0], bl[2 * jp][1], bl[2 * jp + 1][0], bl[2 * jp + 1][1],
                      pBl + jp * 1024 + koB);
            }
#pragma unroll
            for (int i = 0; i < 4; i++) {        // m16 groups: rows +16 each
                LDSM4(ah[i][0], ah[i][1], ah[i][2], ah[i][3], pAh + i * 1024 + koA);
                LDSM4(al[i][0], al[i][1], al[i][2], al[i][3], pAl + i * 1024 + koA);
            }
            // term-major MMA issue: no consecutive same-accumulator ops
#pragma unroll
            for (int i = 0; i < 4; i++)
#pragma unroll
                for (int j = 0; j < 4; j++) MMA16816(acc[i][j], ah[i], bh[j]);
#pragma unroll
            for (int i = 0; i < 4; i++)
#pragma unroll
                for (int j = 0; j < 4; j++) MMA16816(acc[i][j], ah[i], bl[j]);
#pragma unroll
            for (int i = 0; i < 4; i++)
#pragma unroll
                for (int j = 0; j < 4; j++) MMA16816(acc[i][j], al[i], bh[j]);
        }
        buf++; if (buf == 3) buf = 0;
    }

    // ------------------------- epilogue -------------------------
    // acc frag layout: c0:(m=lane/4, n=2(lane%4)) c1:(m,n+1) c2:(m+8,n) c3:(m+8,n+1)
    const int er = lane >> 2;
    const int ec = (lane & 3) * 2;

    if constexpr (MODE == 0) {
#pragma unroll
        for (int i = 0; i < 4; i++)
#pragma unroll
            for (int j = 0; j < 4; j++) {
                size_t r = (size_t)(row0 + wm + i * 16 + er);
                int c = col0 + wn + j * 8 + ec;
                *reinterpret_cast<float2*>(&Cf[r * ldc + c]) =
                    make_float2(acc[i][j][0], acc[i][j][1]);
                *reinterpret_cast<float2*>(&Cf[(r + 8) * ldc + c]) =
                    make_float2(acc[i][j][2], acc[i][j][3]);
            }
    } else {
        __syncthreads();   // all warps done reading pipeline stages before smem reuse
        float* ew = (float*)(smem + warp * 768);   // 16x24 floats = 1536 B per warp
        if constexpr (MODE == 1) {
#pragma unroll
            for (int i = 0; i < 4; i++)
#pragma unroll
                for (int jp = 0; jp < 2; jp++) {
                    int j0 = 2 * jp, j1 = 2 * jp + 1;
                    ew[er * 24 + ec]            = acc[i][j0][0];
                    ew[er * 24 + ec + 1]        = acc[i][j0][1];
                    ew[(er + 8) * 24 + ec]      = acc[i][j0][2];
                    ew[(er + 8) * 24 + ec + 1]  = acc[i][j0][3];
                    ew[er * 24 + 8 + ec]        = acc[i][j1][0];
                    ew[er * 24 + 8 + ec + 1]    = acc[i][j1][1];
                    ew[(er + 8) * 24 + 8 + ec]     = acc[i][j1][2];
                    ew[(er + 8) * 24 + 8 + ec + 1] = acc[i][j1][3];
                    __syncwarp();
                    int r = lane >> 1, cb = (lane & 1) * 8;
                    float v[8];
#pragma unroll
                    for (int e = 0; e < 8; e++) v[e] = ew[r * 24 + cb + e] * alpha;
                    uint4 hp, lp;
                    __nv_bfloat16 h[8];
#pragma unroll
                    for (int e = 0; e < 8; e++) h[e] = __float2bfloat16(v[e]);
                    hp.x = pack_bf2(h[0], h[1]); hp.y = pack_bf2(h[2], h[3]);
                    hp.z = pack_bf2(h[4], h[5]); hp.w = pack_bf2(h[6], h[7]);
                    __nv_bfloat16 l[8];
#pragma unroll
                    for (int e = 0; e < 8; e++) l[e] = __float2bfloat16(v[e] - __bfloat162float(h[e]));
                    lp.x = pack_bf2(l[0], l[1]); lp.y = pack_bf2(l[2], l[3]);
                    lp.z = pack_bf2(l[4], l[5]); lp.w = pack_bf2(l[6], l[7]);
                    size_t idx = (size_t)(row0 + wm + i * 16 + r) * ldo + col0 + wn + jp * 16 + cb;
                    *reinterpret_cast<uint4*>(&Oh[idx]) = hp;
                    *reinterpret_cast<uint4*>(&Ol[idx]) = lp;
                    __syncwarp();
                }
        } else {
            // MODE 2: transposed split (V^T), row0 indexes tokens [B*S]
            const int b  = row0 >> 11;               // SS == 2048
            __nv_bfloat16* ohb = Oh + (size_t)b * UU * SS;
            __nv_bfloat16* olb = Ol + (size_t)b * UU * SS;
#pragma unroll
            for (int i = 0; i < 4; i++)
#pragma unroll
                for (int jp = 0; jp < 2; jp++) {
                    int j0 = 2 * jp, j1 = 2 * jp + 1;
                    ew[er * 24 + ec]            = acc[i][j0][0];
                    ew[er * 24 + ec + 1]        = acc[i][j0][1];
                    ew[(er + 8) * 24 + ec]      = acc[i][j0][2];
                    ew[(er + 8) * 24 + ec + 1]  = acc[i][j0][3];
                    ew[er * 24 + 8 + ec]        = acc[i][j1][0];
                    ew[er * 24 + 8 + ec + 1]    = acc[i][j1][1];
                    ew[(er + 8) * 24 + 8 + ec]     = acc[i][j1][2];
                    ew[(er + 8) * 24 + 8 + ec + 1] = acc[i][j1][3];
                    __syncwarp();
                    if (lane < 16) {
                        int u = lane;
                        float v[16];
#pragma unroll
                        for (int r = 0; r < 16; r++) v[r] = ew[r * 24 + u];
                        uint32_t hw[8], lw[8];
#pragma unroll
                        for (int e = 0; e < 8; e++) {
                            __nv_bfloat16 ha = __float2bfloat16(v[2 * e]);
                            __nv_bfloat16 hb = __float2bfloat16(v[2 * e + 1]);
                            hw[e] = pack_bf2(ha, hb);
                            lw[e] = pack_bf2(__float2bfloat16(v[2 * e] - __bfloat162float(ha)),
                                             __float2bfloat16(v[2 * e + 1] - __bfloat162float(hb)));
                        }
                        int s0 = (row0 & 2047) + wm + i * 16;
                        size_t idx = (size_t)(col0 + wn + jp * 16 + u) * SS + s0;
                        uint4 h0, h1, l0, l1;
                        h0.x = hw[0]; h0.y = hw[1]; h0.z = hw[2]; h0.w = hw[3];
                        h1.x = hw[4]; h1.y = hw[5]; h1.z = hw[6]; h1.w = hw[7];
                        l0.x = lw[0]; l0.y = lw[1]; l0.z = lw[2]; l0.w = lw[3];
                        l1.x = lw[4]; l1.y = lw[5]; l1.z = lw[6]; l1.w = lw[7];
                        *reinterpret_cast<uint4*>(&ohb[idx])     = h0;
                        *reinterpret_cast<uint4*>(&ohb[idx + 8]) = h1;
                        *reinterpret_cast<uint4*>(&olb[idx])     = l0;
                        *reinterpret_cast<uint4*>(&olb[idx + 8]) = l1;
                    }
                    __syncwarp();
                }
        }
    }
}

// ---------------------------------------------------------------------------
// GEMM kernel wrappers (2 CTAs/SM)
// ---------------------------------------------------------------------------

// Combined V^T projection (blocks 0..511) + Mt (blocks 512..527).
__global__ __launch_bounds__(256, 2) void vmt_kernel() {
    int id = blockIdx.x;
    if (id < 512) {
        int row0 = (id >> 2) * 128;       // token tile
        int col0 = (id & 3) * 128;        // u tile
        gemm_mma<2>(row0, col0, g_xh, g_xl, g_wvth, g_wvtl, DD, DD, DD, 1.0f,
                    nullptr, 0, g_vth, g_vtl, SS);
    } else {
        int id2 = id - 512;
        int row0 = (id2 >> 2) * 128;
        int col0 = (id2 & 3) * 128;
        gemm_mma<1>(row0, col0, g_wkh, g_wkl, g_wqh, g_wql, UU, UU, UU, SCALE,
                    nullptr, 0, g_mth, g_mtl, DD);
    }
}

__global__ __launch_bounds__(256, 2) void p_kernel() {
    // P = x @ Mt^T  -> [B*S][D] split
    gemm_mma<1>(blockIdx.y * 128, blockIdx.x * 128,
                g_xh, g_xl, g_mth, g_mtl, DD, DD, DD, 1.0f,
                nullptr, 0, g_ph, g_pl, DD);
}

__global__ __launch_bounds__(256, 2) void scores_kernel(float* __restrict__ attn) {
    const size_t zo = (size_t)blockIdx.z * SS * DD;
    gemm_mma<0>(blockIdx.y * 128, blockIdx.x * 128,
                g_ph + zo, g_pl + zo, g_xh + zo, g_xl + zo, DD, DD, DD, 1.0f,
                attn + (size_t)blockIdx.z * SS * SS, SS, nullptr, nullptr, 0);
}

__global__ __launch_bounds__(256, 2) void context_kernel(float* __restrict__ ctx) {
    const size_t z = blockIdx.z;
    gemm_mma<0>(blockIdx.y * 128, blockIdx.x * 128,
                g_ah + z * (size_t)SS * SS, g_al + z * (size_t)SS * SS,
                g_vth + z * (size_t)UU * SS, g_vtl + z * (size_t)UU * SS,
                SS, SS, SS, 1.0f,
                ctx + z * (size_t)SS * UU, UU, nullptr, nullptr, 0);
}

// ---------------------------------------------------------------------------
// Elementwise kernels
// ---------------------------------------------------------------------------
__global__ __launch_bounds__(256) void split_x_kernel(const float* __restrict__ in) {
    int i = blockIdx.x * 256 + threadIdx.x;     // float4 granules, NX/4 total
    float4 v = reinterpret_cast<const float4*>(in)[i];
    __nv_bfloat16 h0 = __float2bfloat16(v.x), h1 = __float2bfloat16(v.y);
    __nv_bfloat16 h2 = __float2bfloat16(v.z), h3 = __float2bfloat16(v.w);
    uint2 hp, lp;
    hp.x = pack_bf2(h0, h1); hp.y = pack_bf2(h2, h3);
    lp.x = pack_bf2(__float2bfloat16(v.x - __bfloat162float(h0)),
                    __float2bfloat16(v.y - __bfloat162float(h1)));
    lp.y = pack_bf2(__float2bfloat16(v.z - __bfloat162float(h2)),
                    __float2bfloat16(v.w - __bfloat162float(h3)));
    reinterpret_cast<uint2*>(g_xh)[i] = hp;
    reinterpret_cast<uint2*>(g_xl)[i] = lp;
}

__global__ __launch_bounds__(256) void splitW_kernel(const float* __restrict__ wq,
                                                     const float* __restrict__ wk) {
    const float* src = (blockIdx.y == 0) ? wq : wk;
    __nv_bfloat16* oh = (blockIdx.y == 0) ? g_wqh : g_wkh;
    __nv_bfloat16* ol = (blockIdx.y == 0) ? g_wql : g_wkl;
    int i = blockIdx.x * 256 + threadIdx.x;     // NW/4 granules
    float4 v = reinterpret_cast<const float4*>(src)[i];
    __nv_bfloat16 h0 = __float2bfloat16(v.x), h1 = __float2bfloat16(v.y);
    __nv_bfloat16 h2 = __float2bfloat16(v.z), h3 = __float2bfloat16(v.w);
    uint2 hp, lp;
    hp.x = pack_bf2(h0, h1); hp.y = pack_bf2(h2, h3);
    lp.x = pack_bf2(__float2bfloat16(v.x - __bfloat162float(h0)),
                    __float2bfloat16(v.y - __bfloat162float(h1)));
    lp.y = pack_bf2(__float2bfloat16(v.z - __bfloat162float(h2)),
                    __float2bfloat16(v.w - __bfloat162float(h3)));
    reinterpret_cast<uint2*>(oh)[i] = hp;
    reinterpret_cast<uint2*>(ol)[i] = lp;
}

__global__ void wsplitT_kernel(const float* __restrict__ wv) {
    __shared__ float t[32][33];
    const int u0 = blockIdx.x * 32, d0 = blockIdx.y * 32;
    const int tx = threadIdx.x, ty = threadIdx.y;
#pragma unroll
    for (int p = 0; p < 4; p++)
        t[ty + p * 8][tx] = wv[(size_t)(d0 + ty + p * 8) * UU + u0 + tx];
    __syncthreads();
#pragma unroll
    for (int p = 0; p < 4; p++) {
        float v = t[tx][ty + p * 8];
        __nv_bfloat16 h = __float2bfloat16(v);
        size_t idx = (size_t)(u0 + ty + p * 8) * DD + d0 + tx;
        g_wvth[idx] = h;
        g_wvtl[idx] = __float2bfloat16(v - __bfloat162float(h));
    }
}

__device__ __forceinline__ float warp_max(float v) {
#pragma unroll
    for (int o = 16; o > 0; o >>= 1) v = fmaxf(v, __shfl_xor_sync(0xffffffffu, v, o));
    return v;
}
__device__ __forceinline__ float warp_sum(float v) {
#pragma unroll
    for (int o = 16; o > 0; o >>= 1) v += __shfl_xor_sync(0xffffffffu, v, o);
    return v;
}

// Row softmax + bf16 hi/lo split, fully vectorized: thread t owns the 8
// contiguous columns [8t, 8t+8) -> float4 loads/stores, uint4 split stores.
__global__ __launch_bounds__(256) void softmax_split_kernel(float* __restrict__ attn) {
    const size_t rowbase = (size_t)blockIdx.x * SS;
    float* p = attn + rowbase;
    const int tid = threadIdx.x;
    const int c0 = tid * 8;
    __shared__ float red[8];

    float4 va = *reinterpret_cast<const float4*>(&p[c0]);
    float4 vb = *reinterpret_cast<const float4*>(&p[c0 + 4]);
    float v[8] = {va.x, va.y, va.z, va.w, vb.x, vb.y, vb.z, vb.w};

    float m = v[0];
#pragma unroll
    for (int j = 1; j < 8; j++) m = fmaxf(m, v[j]);
    m = warp_max(m);
    if ((tid & 31) == 0) red[tid >> 5] = m;
    __syncthreads();
    if (tid < 32) {
        float t = (tid < 8) ? red[tid] : -INFINITY;
        t = warp_max(t);
        if (tid == 0) red[0] = t;
    }
    __syncthreads();
    m = red[0];

    float s = 0.0f;
#pragma unroll
    for (int j = 0; j < 8; j++) { v[j] = __expf(v[j] - m); s += v[j]; }
    s = warp_sum(s);
    __syncthreads();
    if ((tid & 31) == 0) red[tid >> 5] = s;
    __syncthreads();
    if (tid < 32) {
        float t = (tid < 8) ? red[tid] : 0.0f;
        t = warp_sum(t);
        if (tid == 0) red[0] = t;
    }
    __syncthreads();
    const float inv = 1.0f / red[0];

    float r[8];
#pragma unroll
    for (int j = 0; j < 8; j++) r[j] = v[j] * inv;

    *reinterpret_cast<float4*>(&p[c0])     = make_float4(r[0], r[1], r[2], r[3]);
    *reinterpret_cast<float4*>(&p[c0 + 4]) = make_float4(r[4], r[5], r[6], r[7]);

    __nv_bfloat16 h[8];
#pragma unroll
    for (int j = 0; j < 8; j++) h[j] = __float2bfloat16(r[j]);
    uint4 hp, lp;
    hp.x = pack_bf2(h[0], h[1]); hp.y = pack_bf2(h[2], h[3]);
    hp.z = pack_bf2(h[4], h[5]); hp.w = pack_bf2(h[6], h[7]);
    __nv_bfloat16 l[8];
#pragma unroll
    for (int j = 0; j < 8; j++) l[j] = __float2bfloat16(r[j] - __bfloat162float(h[j]));
    lp.x = pack_bf2(l[0], l[1]); lp.y = pack_bf2(l[2], l[3]);
    lp.z = pack_bf2(l[4], l[5]); lp.w = pack_bf2(l[6], l[7]);
    *reinterpret_cast<uint4*>(&g_ah[rowbase + c0]) = hp;
    *reinterpret_cast<uint4*>(&g_al[rowbase + c0]) = lp;
}

// ---------------------------------------------------------------------------
extern "C" void kernel_launch(void* const* d_in, const int* in_sizes, int n_in,
                              void* d_out, int out_size) {
    const float* x  = (const float*)d_in[0];   // [B,S,D]
    const float* wq = (const float*)d_in[1];   // [D,U]
    const float* wk = (const float*)d_in[2];
    const float* wv = (const float*)d_in[3];

    float* out  = (float*)d_out;
    float* ctx  = out;                         // [B,S,U]
    float* attn = out + NX;                    // [B,S,S]

    cudaFuncSetAttribute(vmt_kernel,     cudaFuncAttributeMaxDynamicSharedMemorySize, SMEM_DYN);
    cudaFuncSetAttribute(p_kernel,       cudaFuncAttributeMaxDynamicSharedMemorySize, SMEM_DYN);
    cudaFuncSetAttribute(scores_kernel,  cudaFuncAttributeMaxDynamicSharedMemorySize, SMEM_DYN);
    cudaFuncSetAttribute(context_kernel, cudaFuncAttributeMaxDynamicSharedMemorySize, SMEM_DYN);

    // 1. splits: x, Wq, Wk (plain), Wv (transposed)
    split_x_kernel<<<(int)(NX / 4 / 256), 256>>>(x);
    splitW_kernel<<<dim3((int)(NW / 4 / 256), 2), 256>>>(wq, wk);
    wsplitT_kernel<<<dim3(UU / 32, DD / 32), dim3(32, 8)>>>(wv);

    // 2. V^T = (x @ Wv)^T  and  Mt = scale * Wk @ Wq^T  (one launch)
    vmt_kernel<<<dim3(528), 256, SMEM_DYN>>>();

    // 3. P = x @ Mt^T  [16384x512]
    p_kernel<<<dim3(4, 128), 256, SMEM_DYN>>>();

    // 4. scores = P @ x^T per batch (scale already folded into Mt)
    scores_kernel<<<dim3(16, 16, BB), 256, SMEM_DYN>>>(attn);

    // 5. softmax + bf16 hi/lo split of attn
    softmax_split_kernel<<<dim3(BB * SS), 256>>>(attn);

    // 6. context = attn @ V per batch
    context_kernel<<<dim3(4, 16, BB), 256, SMEM_DYN>>>(ctx);
}

// round 12
// speedup vs baseline: 2.0590x; 1.7341x over previous
#include <cuda_runtime.h>
#include <cuda_bf16.h>
#include <cuda_fp16.h>
#include <cstdint>
#include <math.h>

// Problem constants
#define BB 8
#define SS 2048
#define DD 512
#define UU 512

#define NX ((size_t)BB * SS * DD)      // 8388608
#define NW ((size_t)DD * UU)           // 262144
#define NA ((size_t)BB * SS * SS)      // 33554432

#define SCALE 0.04419417382415922f    // 1/sqrt(512)

// ---------------------------------------------------------------------------
// Device-global scratch (no allocations allowed)
// ---------------------------------------------------------------------------
__device__ __align__(128) __nv_bfloat16 g_xh[NX],  g_xl[NX];     // x splits [B*S][D] (bf16x3 A operand)
__device__ __align__(128) __nv_bfloat16 g_wqh[NW], g_wql[NW];    // Wq splits [D][U]
__device__ __align__(128) __nv_bfloat16 g_wkh[NW], g_wkl[NW];    // Wk splits [D][U]
__device__ __align__(128) __nv_bfloat16 g_wvth[NW], g_wvtl[NW];  // Wv^T splits [U][D]
__device__ __align__(128) __nv_bfloat16 g_mth[NW], g_mtl[NW];    // Mt = scale*Wk Wq^T [D][D]
__device__ __align__(128) __half g_xf[NX];                       // x fp16 (scores B operand)
__device__ __align__(128) __half g_pf[NX];                       // P = x Mt^T fp16 [B*S][D]
__device__ __align__(128) __half g_vtf[NX];                      // V^T fp16 [B][U][S]
__device__ __align__(128) __half g_af[NA];                       // attn fp16 [B][S][S]

// ---------------------------------------------------------------------------
// Helpers
// ---------------------------------------------------------------------------
__device__ __forceinline__ uint32_t smem_u32(const void* p) {
    uint32_t a;
    asm("{ .reg .u64 t; cvta.to.shared.u64 t, %1; cvt.u32.u64 %0, t; }" : "=r"(a) : "l"(p));
    return a;
}
__device__ __forceinline__ uint32_t pack_bf2(__nv_bfloat16 a, __nv_bfloat16 b) {
    return (uint32_t)__bfloat16_as_ushort(a) | ((uint32_t)__bfloat16_as_ushort(b) << 16);
}
__device__ __forceinline__ uint32_t pack_h2(float a, float b) {
    __half2 h = __floats2half2_rn(a, b);
    return *reinterpret_cast<uint32_t*>(&h);
}

#define LDSM4(r0, r1, r2, r3, addr) \
    asm volatile("ldmatrix.sync.aligned.m8n8.x4.shared.b16 {%0,%1,%2,%3}, [%4];" \
        : "=r"(r0), "=r"(r1), "=r"(r2), "=r"(r3) : "r"(addr))

#define MMA16816(d, a, b) \
    asm("mma.sync.aligned.m16n8k16.row.col.f32.bf16.bf16.f32 " \
        "{%0,%1,%2,%3}, {%4,%5,%6,%7}, {%8,%9}, {%0,%1,%2,%3};" \
        : "+f"((d)[0]), "+f"((d)[1]), "+f"((d)[2]), "+f"((d)[3]) \
        : "r"((a)[0]), "r"((a)[1]), "r"((a)[2]), "r"((a)[3]), \
          "r"((b)[0]), "r"((b)[1]))

#define MMAH16816(d, a, b) \
    asm("mma.sync.aligned.m16n8k16.row.col.f32.f16.f16.f32 " \
        "{%0,%1,%2,%3}, {%4,%5,%6,%7}, {%8,%9}, {%0,%1,%2,%3};" \
        : "+f"((d)[0]), "+f"((d)[1]), "+f"((d)[2]), "+f"((d)[3]) \
        : "r"((a)[0]), "r"((a)[1]), "r"((a)[2]), "r"((a)[3]), \
          "r"((b)[0]), "r"((b)[1]))

// ---------------------------------------------------------------------------
// Common: 128x128 CTA tile, BK=32, 256 threads (8 warps 2x4, 64x32 warp tile),
// 3-stage cp.async pipeline, 2 CTAs/SM.  64B smem rows, XOR swizzle
// phys_chunk = c ^ ((r>>1)&3).  Operands K-major; C = A * B^T.
// ---------------------------------------------------------------------------
#define ARR_B 8192                      // 128 rows * 64 bytes per array
#define STG_B 32768                     // 4 arrays per stage (bf16x3 engine)
#define SMEM_DYN (3 * STG_B)            // 98304 bytes
#define STGF_B 16384                    // 2 arrays per stage (fp16 engine)
#define SMEM_F16 (3 * STGF_B)           // 49152 bytes

template <typename T>
__device__ __forceinline__ void stage_arr(uint32_t sdst, const T* __restrict__ src,
                                          int r0, int k0, int ld, int tid) {
#pragma unroll
    for (int j = 0; j < 2; j++) {
        int idx = tid + j * 256;                  // 512 chunks of 16B
        int r = idx >> 2, c = idx & 3;
        int phys = c ^ ((r >> 1) & 3);
        uint32_t dst = sdst + (uint32_t)(r * 64 + phys * 16);
        const void* gp = (const void*)(src + (size_t)(r0 + r) * ld + k0 + c * 8);
        asm volatile("cp.async.cg.shared.global [%0], [%1], 16;" :: "r"(dst), "l"(gp));
    }
}

__device__ __forceinline__ void stage_all(uint32_t sb,
                                          const __nv_bfloat16* Ah, const __nv_bfloat16* Al,
                                          const __nv_bfloat16* Bh, const __nv_bfloat16* Bl,
                                          int row0, int col0, int k0, int lda, int ldb, int tid) {
    stage_arr(sb + 0 * ARR_B, Ah, row0, k0, lda, tid);
    stage_arr(sb + 1 * ARR_B, Al, row0, k0, lda, tid);
    stage_arr(sb + 2 * ARR_B, Bh, col0, k0, ldb, tid);
    stage_arr(sb + 3 * ARR_B, Bl, col0, k0, ldb, tid);
    asm volatile("cp.async.commit_group;" ::: "memory");
}

// ---------------------------------------------------------------------------
// bf16x3 engine.  MODE 1: bf16 hi/lo split store (alpha-scaled).
// MODE 3: fp16 single store (alpha-scaled).  MODE 4: fp16 single TRANSPOSED.
// ---------------------------------------------------------------------------
template <int MODE>
__device__ __forceinline__ void gemm_mma(int row0, int col0,
                                         const __nv_bfloat16* __restrict__ Ah,
                                         const __nv_bfloat16* __restrict__ Al,
                                         const __nv_bfloat16* __restrict__ Bh,
                                         const __nv_bfloat16* __restrict__ Bl,
                                         int K, int lda, int ldb, float alpha,
                                         __nv_bfloat16* __restrict__ Oh,
                                         __nv_bfloat16* __restrict__ Ol, int ldo) {
    extern __shared__ __nv_bfloat16 smem[];

    const int tid  = threadIdx.x;
    const int warp = tid >> 5;
    const int lane = tid & 31;
    const int wm = (warp >> 2) * 64;     // warp row: 0 / 64
    const int wn = (warp & 3) * 32;      // warp col: 0..96

    const uint32_t sbase = smem_u32(smem);

    const int aRow = wm + ((lane >> 3) & 1) * 8 + (lane & 7);
    const uint32_t aOff = (uint32_t)(aRow * 64);
    const uint32_t aS   = (uint32_t)((aRow >> 1) & 3);
    const uint32_t aK   = (uint32_t)(lane >> 4);
    const int bRow = wn + ((lane >> 4) & 1) * 8 + (lane & 7);
    const uint32_t bOff = (uint32_t)(bRow * 64);
    const uint32_t bS   = (uint32_t)((bRow >> 1) & 3);
    const uint32_t bK   = (uint32_t)((lane >> 3) & 1);

    float acc[4][4][4];
#pragma unroll
    for (int i = 0; i < 4; i++)
#pragma unroll
        for (int j = 0; j < 4; j++)
#pragma unroll
            for (int e = 0; e < 4; e++) acc[i][j][e] = 0.0f;

    const int niter = K >> 5;

    stage_all(sbase, Ah, Al, Bh, Bl, row0, col0, 0, lda, ldb, tid);
    stage_all(sbase + STG_B, Ah, Al, Bh, Bl, row0, col0, 32, lda, ldb, tid);

    int buf = 0;
    for (int it = 0; it < niter; it++) {
        if (it + 1 < niter) {
            asm volatile("cp.async.wait_group 1;" ::: "memory");
        } else {
            asm volatile("cp.async.wait_group 0;" ::: "memory");
        }
        __syncthreads();
        if (it + 2 < niter) {
            int nb = buf + 2; if (nb >= 3) nb -= 3;
            stage_all(sbase + (uint32_t)(nb * STG_B), Ah, Al, Bh, Bl,
                      row0, col0, (it + 2) << 5, lda, ldb, tid);
        }

        const uint32_t base = sbase + (uint32_t)(buf * STG_B);
        const uint32_t pAh = base + 0 * ARR_B + aOff;
        const uint32_t pAl = base + 1 * ARR_B + aOff;
        const uint32_t pBh = base + 2 * ARR_B + bOff;
        const uint32_t pBl = base + 3 * ARR_B + bOff;

#pragma unroll
        for (int ks = 0; ks < 2; ks++) {
            const uint32_t koA = (((ks * 2 + aK) ^ aS) << 4);
            const uint32_t koB = (((ks * 2 + bK) ^ bS) << 4);
            uint32_t ah[4][4], al[4][4];
            uint32_t bh[4][2], bl[4][2];
#pragma unroll
            for (int jp = 0; jp < 2; jp++) {
                LDSM4(bh[2 * jp][0], bh[2 * jp][1], bh[2 * jp + 1][0], bh[2 * jp + 1][1],
                      pBh + jp * 1024 + koB);
                LDSM4(bl[2 * jp][0], bl[2 * jp][1], bl[2 * jp + 1][0], bl[2 * jp + 1][1],
                      pBl + jp * 1024 + koB);
            }
#pragma unroll
            for (int i = 0; i < 4; i++) {
                LDSM4(ah[i][0], ah[i][1], ah[i][2], ah[i][3], pAh + i * 1024 + koA);
                LDSM4(al[i][0], al[i][1], al[i][2], al[i][3], pAl + i * 1024 + koA);
            }
#pragma unroll
            for (int i = 0; i < 4; i++)
#pragma unroll
                for (int j = 0; j < 4; j++) MMA16816(acc[i][j], ah[i], bh[j]);
#pragma unroll
            for (int i = 0; i < 4; i++)
#pragma unroll
                for (int j = 0; j < 4; j++) MMA16816(acc[i][j], ah[i], bl[j]);
#pragma unroll
            for (int i = 0; i < 4; i++)
#pragma unroll
                for (int j = 0; j < 4; j++) MMA16816(acc[i][j], al[i], bh[j]);
        }
        buf++; if (buf == 3) buf = 0;
    }

    // ------------------------- epilogue -------------------------
    const int er = lane >> 2;
    const int ec = (lane & 3) * 2;

    if constexpr (MODE == 3) {
        // fp16 single direct store
        __half* Of = reinterpret_cast<__half*>(Oh);
#pragma unroll
        for (int i = 0; i < 4; i++)
#pragma unroll
            for (int j = 0; j < 4; j++) {
                size_t r = (size_t)(row0 + wm + i * 16 + er);
                int c = col0 + wn + j * 8 + ec;
                *reinterpret_cast<uint32_t*>(&Of[r * ldo + c]) =
                    pack_h2(acc[i][j][0] * alpha, acc[i][j][1] * alpha);
                *reinterpret_cast<uint32_t*>(&Of[(r + 8) * ldo + c]) =
                    pack_h2(acc[i][j][2] * alpha, acc[i][j][3] * alpha);
            }
    } else {
        __syncthreads();   // all warps done with pipeline smem before reuse
        float* ew = (float*)(smem + warp * 768);   // 16x24 floats per warp
        if constexpr (MODE == 1) {
#pragma unroll
            for (int i = 0; i < 4; i++)
#pragma unroll
                for (int jp = 0; jp < 2; jp++) {
                    int j0 = 2 * jp, j1 = 2 * jp + 1;
                    ew[er * 24 + ec]            = acc[i][j0][0];
                    ew[er * 24 + ec + 1]        = acc[i][j0][1];
                    ew[(er + 8) * 24 + ec]      = acc[i][j0][2];
                    ew[(er + 8) * 24 + ec + 1]  = acc[i][j0][3];
                    ew[er * 24 + 8 + ec]        = acc[i][j1][0];
                    ew[er * 24 + 8 + ec + 1]    = acc[i][j1][1];
                    ew[(er + 8) * 24 + 8 + ec]     = acc[i][j1][2];
                    ew[(er + 8) * 24 + 8 + ec + 1] = acc[i][j1][3];
                    __syncwarp();
                    int r = lane >> 1, cb = (lane & 1) * 8;
                    float v[8];
#pragma unroll
                    for (int e = 0; e < 8; e++) v[e] = ew[r * 24 + cb + e] * alpha;
                    uint4 hp, lp;
                    __nv_bfloat16 h[8];
#pragma unroll
                    for (int e = 0; e < 8; e++) h[e] = __float2bfloat16(v[e]);
                    hp.x = pack_bf2(h[0], h[1]); hp.y = pack_bf2(h[2], h[3]);
                    hp.z = pack_bf2(h[4], h[5]); hp.w = pack_bf2(h[6], h[7]);
                    __nv_bfloat16 l[8];
#pragma unroll
                    for (int e = 0; e < 8; e++) l[e] = __float2bfloat16(v[e] - __bfloat162float(h[e]));
                    lp.x = pack_bf2(l[0], l[1]); lp.y = pack_bf2(l[2], l[3]);
                    lp.z = pack_bf2(l[4], l[5]); lp.w = pack_bf2(l[6], l[7]);
                    size_t idx = (size_t)(row0 + wm + i * 16 + r) * ldo + col0 + wn + jp * 16 + cb;
                    *reinterpret_cast<uint4*>(&Oh[idx]) = hp;
                    *reinterpret_cast<uint4*>(&Ol[idx]) = lp;
                    __syncwarp();
                }
        } else {
            // MODE 4: fp16 single TRANSPOSED store (V^T), row0 indexes tokens
            const int b  = row0 >> 11;               // SS == 2048
            __half* Of = reinterpret_cast<__half*>(Oh) + (size_t)b * UU * SS;
#pragma unroll
            for (int i = 0; i < 4; i++)
#pragma unroll
                for (int jp = 0; jp < 2; jp++) {
                    int j0 = 2 * jp, j1 = 2 * jp + 1;
                    ew[er * 24 + ec]            = acc[i][j0][0];
                    ew[er * 24 + ec + 1]        = acc[i][j0][1];
                    ew[(er + 8) * 24 + ec]      = acc[i][j0][2];
                    ew[(er + 8) * 24 + ec + 1]  = acc[i][j0][3];
                    ew[er * 24 + 8 + ec]        = acc[i][j1][0];
                    ew[er * 24 + 8 + ec + 1]    = acc[i][j1][1];
                    ew[(er + 8) * 24 + 8 + ec]     = acc[i][j1][2];
                    ew[(er + 8) * 24 + 8 + ec + 1] = acc[i][j1][3];
                    __syncwarp();
                    if (lane < 16) {
                        int u = lane;
                        float v[16];
#pragma unroll
                        for (int r = 0; r < 16; r++) v[r] = ew[r * 24 + u];
                        uint32_t hw[8];
#pragma unroll
                        for (int e = 0; e < 8; e++) hw[e] = pack_h2(v[2 * e], v[2 * e + 1]);
                        int s0 = (row0 & 2047) + wm + i * 16;
                        size_t idx = (size_t)(col0 + wn + jp * 16 + u) * SS + s0;
                        uint4 h0, h1;
                        h0.x = hw[0]; h0.y = hw[1]; h0.z = hw[2]; h0.w = hw[3];
                        h1.x = hw[4]; h1.y = hw[5]; h1.z = hw[6]; h1.w = hw[7];
                        *reinterpret_cast<uint4*>(&Of[idx])     = h0;
                        *reinterpret_cast<uint4*>(&Of[idx + 8]) = h1;
                    }
                    __syncwarp();
                }
        }
    }
}

// ---------------------------------------------------------------------------
// fp16 single-term engine: same pipeline, 2 arrays per stage, fp32 out.
// ---------------------------------------------------------------------------
__device__ __forceinline__ void gemm_f16(int row0, int col0,
                                         const __half* __restrict__ Af,
                                         const __half* __restrict__ Bf,
                                         int K, int lda, int ldb,
                                         float* __restrict__ Cf, int ldc) {
    extern __shared__ __nv_bfloat16 smem[];

    const int tid  = threadIdx.x;
    const int warp = tid >> 5;
    const int lane = tid & 31;
    const int wm = (warp >> 2) * 64;
    const int wn = (warp & 3) * 32;

    const uint32_t sbase = smem_u32(smem);

    const int aRow = wm + ((lane >> 3) & 1) * 8 + (lane & 7);
    const uint32_t aOff = (uint32_t)(aRow * 64);
    const uint32_t aS   = (uint32_t)((aRow >> 1) & 3);
    const uint32_t aK   = (uint32_t)(lane >> 4);
    const int bRow = wn + ((lane >> 4) & 1) * 8 + (lane & 7);
    const uint32_t bOff = (uint32_t)(bRow * 64);
    const uint32_t bS   = (uint32_t)((bRow >> 1) & 3);
    const uint32_t bK   = (uint32_t)((lane >> 3) & 1);

    float acc[4][4][4];
#pragma unroll
    for (int i = 0; i < 4; i++)
#pragma unroll
        for (int j = 0; j < 4; j++)
#pragma unroll
            for (int e = 0; e < 4; e++) acc[i][j][e] = 0.0f;

    const int niter = K >> 5;

    // prologue: stage iters 0,1
    {
        stage_arr(sbase + 0 * ARR_B, Af, row0, 0, lda, tid);
        stage_arr(sbase + 1 * ARR_B, Bf, col0, 0, ldb, tid);
        asm volatile("cp.async.commit_group;" ::: "memory");
        stage_arr(sbase + STGF_B + 0 * ARR_B, Af, row0, 32, lda, tid);
        stage_arr(sbase + STGF_B + 1 * ARR_B, Bf, col0, 32, ldb, tid);
        asm volatile("cp.async.commit_group;" ::: "memory");
    }

    int buf = 0;
    for (int it = 0; it < niter; it++) {
        if (it + 1 < niter) {
            asm volatile("cp.async.wait_group 1;" ::: "memory");
        } else {
            asm volatile("cp.async.wait_group 0;" ::: "memory");
        }
        __syncthreads();
        if (it + 2 < niter) {
            int nb = buf + 2; if (nb >= 3) nb -= 3;
            uint32_t sb = sbase + (uint32_t)(nb * STGF_B);
            int k0 = (it + 2) << 5;
            stage_arr(sb + 0 * ARR_B, Af, row0, k0, lda, tid);
            stage_arr(sb + 1 * ARR_B, Bf, col0, k0, ldb, tid);
            asm volatile("cp.async.commit_group;" ::: "memory");
        }

        const uint32_t base = sbase + (uint32_t)(buf * STGF_B);
        const uint32_t pA = base + 0 * ARR_B + aOff;
        const uint32_t pB = base + 1 * ARR_B + bOff;

#pragma unroll
        for (int ks = 0; ks < 2; ks++) {
            const uint32_t koA = (((ks * 2 + aK) ^ aS) << 4);
            const uint32_t koB = (((ks * 2 + bK) ^ bS) << 4);
            uint32_t ah[4][4];
            uint32_t bh[4][2];
#pragma unroll
            for (int jp = 0; jp < 2; jp++) {
                LDSM4(bh[2 * jp][0], bh[2 * jp][1], bh[2 * jp + 1][0], bh[2 * jp + 1][1],
                      pB + jp * 1024 + koB);
            }
#pragma unroll
            for (int i = 0; i < 4; i++) {
                LDSM4(ah[i][0], ah[i][1], ah[i][2], ah[i][3], pA + i * 1024 + koA);
            }
#pragma unroll
            for (int i = 0; i < 4; i++)
#pragma unroll
                for (int j = 0; j < 4; j++) MMAH16816(acc[i][j], ah[i], bh[j]);
        }
        buf++; if (buf == 3) buf = 0;
    }

    // epilogue: fp32 store
    const int er = lane >> 2;
    const int ec = (lane & 3) * 2;
#pragma unroll
    for (int i = 0; i < 4; i++)
#pragma unroll
        for (int j = 0; j < 4; j++) {
            size_t r = (size_t)(row0 + wm + i * 16 + er);
            int c = col0 + wn + j * 8 + ec;
            *reinterpret_cast<float2*>(&Cf[r * ldc + c]) =
                make_float2(acc[i][j][0], acc[i][j][1]);
            *reinterpret_cast<float2*>(&Cf[(r + 8) * ldc + c]) =
                make_float2(acc[i][j][2], acc[i][j][3]);
        }
}

// ---------------------------------------------------------------------------
// GEMM kernel wrappers (2 CTAs/SM)
// ---------------------------------------------------------------------------

// Combined V^T projection fp16 (blocks 0..511) + Mt bf16-pair (blocks 512..527).
__global__ __launch_bounds__(256, 2) void vmt_kernel() {
    int id = blockIdx.x;
    if (id < 512) {
        int row0 = (id >> 2) * 128;       // token tile
        int col0 = (id & 3) * 128;        // u tile
        gemm_mma<4>(row0, col0, g_xh, g_xl, g_wvth, g_wvtl, DD, DD, DD, 1.0f,
                    (__nv_bfloat16*)g_vtf, nullptr, SS);
    } else {
        int id2 = id - 512;
        int row0 = (id2 >> 2) * 128;
        int col0 = (id2 & 3) * 128;
        gemm_mma<1>(row0, col0, g_wkh, g_wkl, g_wqh, g_wql, UU, UU, UU, SCALE,
                    g_mth, g_mtl, DD);
    }
}

__global__ __launch_bounds__(256, 2) void p_kernel() {
    // P = x @ Mt^T  -> fp16 [B*S][D]
    gemm_mma<3>(blockIdx.y * 128, blockIdx.x * 128,
                g_xh, g_xl, g_mth, g_mtl, DD, DD, DD, 1.0f,
                (__nv_bfloat16*)g_pf, nullptr, DD);
}

__global__ __launch_bounds__(256, 2) void scores_kernel(float* __restrict__ attn) {
    const size_t zo = (size_t)blockIdx.z * SS * DD;
    gemm_f16(blockIdx.y * 128, blockIdx.x * 128,
             g_pf + zo, g_xf + zo, DD, DD, DD,
             attn + (size_t)blockIdx.z * SS * SS, SS);
}

__global__ __launch_bounds__(256, 2) void context_kernel(float* __restrict__ ctx) {
    const size_t z = blockIdx.z;
    gemm_f16(blockIdx.y * 128, blockIdx.x * 128,
             g_af + z * (size_t)SS * SS, g_vtf + z * (size_t)UU * SS,
             SS, SS, SS,
             ctx + z * (size_t)SS * UU, UU);
}

// ---------------------------------------------------------------------------
// Elementwise kernels
// ---------------------------------------------------------------------------
__global__ __launch_bounds__(256) void split_x_kernel(const float* __restrict__ in) {
    int i = blockIdx.x * 256 + threadIdx.x;     // float4 granules, NX/4 total
    float4 v = reinterpret_cast<const float4*>(in)[i];
    __nv_bfloat16 h0 = __float2bfloat16(v.x), h1 = __float2bfloat16(v.y);
    __nv_bfloat16 h2 = __float2bfloat16(v.z), h3 = __float2bfloat16(v.w);
    uint2 hp, lp;
    hp.x = pack_bf2(h0, h1); hp.y = pack_bf2(h2, h3);
    lp.x = pack_bf2(__float2bfloat16(v.x - __bfloat162float(h0)),
                    __float2bfloat16(v.y - __bfloat162float(h1)));
    lp.y = pack_bf2(__float2bfloat16(v.z - __bfloat162float(h2)),
                    __float2bfloat16(v.w - __bfloat162float(h3)));
    reinterpret_cast<uint2*>(g_xh)[i] = hp;
    reinterpret_cast<uint2*>(g_xl)[i] = lp;
    uint2 fp;
    fp.x = pack_h2(v.x, v.y);
    fp.y = pack_h2(v.z, v.w);
    reinterpret_cast<uint2*>(g_xf)[i] = fp;
}

__global__ __launch_bounds__(256) void splitW_kernel(const float* __restrict__ wq,
                                                     const float* __restrict__ wk) {
    const float* src = (blockIdx.y == 0) ? wq : wk;
    __nv_bfloat16* oh = (blockIdx.y == 0) ? g_wqh : g_wkh;
    __nv_bfloat16* ol = (blockIdx.y == 0) ? g_wql : g_wkl;
    int i = blockIdx.x * 256 + threadIdx.x;     // NW/4 granules
    float4 v = reinterpret_cast<const float4*>(src)[i];
    __nv_bfloat16 h0 = __float2bfloat16(v.x), h1 = __float2bfloat16(v.y);
    __nv_bfloat16 h2 = __float2bfloat16(v.z), h3 = __float2bfloat16(v.w);
    uint2 hp, lp;
    hp.x = pack_bf2(h0, h1); hp.y = pack_bf2(h2, h3);
    lp.x = pack_bf2(__float2bfloat16(v.x - __bfloat162float(h0)),
                    __float2bfloat16(v.y - __bfloat162float(h1)));
    lp.y = pack_bf2(__float2bfloat16(v.z - __bfloat162float(h2)),
                    __float2bfloat16(v.w - __bfloat162float(h3)));
    reinterpret_cast<uint2*>(oh)[i] = hp;
    reinterpret_cast<uint2*>(ol)[i] = lp;
}

__global__ void wsplitT_kernel(const float* __restrict__ wv) {
    __shared__ float t[32][33];
    const int u0 = blockIdx.x * 32, d0 = blockIdx.y * 32;
    const int tx = threadIdx.x, ty = threadIdx.y;
#pragma unroll
    for (int p = 0; p < 4; p++)
        t[ty + p * 8][tx] = wv[(size_t)(d0 + ty + p * 8) * UU + u0 + tx];
    __syncthreads();
#pragma unroll
    for (int p = 0; p < 4; p++) {
        float v = t[tx][ty + p * 8];
        __nv_bfloat16 h = __float2bfloat16(v);
        size_t idx = (size_t)(u0 + ty + p * 8) * DD + d0 + tx;
        g_wvth[idx] = h;
        g_wvtl[idx] = __float2bfloat16(v - __bfloat162float(h));
    }
}

__device__ __forceinline__ float warp_max(float v) {
#pragma unroll
    for (int o = 16; o > 0; o >>= 1) v = fmaxf(v, __shfl_xor_sync(0xffffffffu, v, o));
    return v;
}
__device__ __forceinline__ float warp_sum(float v) {
#pragma unroll
    for (int o = 16; o > 0; o >>= 1) v += __shfl_xor_sync(0xffffffffu, v, o);
    return v;
}

// Row softmax + fp16 store, vectorized: thread t owns 8 contiguous columns.
__global__ __launch_bounds__(256) void softmax_split_kernel(float* __restrict__ attn) {
    const size_t rowbase = (size_t)blockIdx.x * SS;
    float* p = attn + rowbase;
    const int tid = threadIdx.x;
    const int c0 = tid * 8;
    __shared__ float red[8];

    float4 va = *reinterpret_cast<const float4*>(&p[c0]);
    float4 vb = *reinterpret_cast<const float4*>(&p[c0 + 4]);
    float v[8] = {va.x, va.y, va.z, va.w, vb.x, vb.y, vb.z, vb.w};

    float m = v[0];
#pragma unroll
    for (int j = 1; j < 8; j++) m = fmaxf(m, v[j]);
    m = warp_max(m);
    if ((tid & 31) == 0) red[tid >> 5] = m;
    __syncthreads();
    if (tid < 32) {
        float t = (tid < 8) ? red[tid] : -INFINITY;
        t = warp_max(t);
        if (tid == 0) red[0] = t;
    }
    __syncthreads();
    m = red[0];

    float s = 0.0f;
#pragma unroll
    for (int j = 0; j < 8; j++) { v[j] = __expf(v[j] - m); s += v[j]; }
    s = warp_sum(s);
    __syncthreads();
    if ((tid & 31) == 0) red[tid >> 5] = s;
    __syncthreads();
    if (tid < 32) {
        float t = (tid < 8) ? red[tid] : 0.0f;
        t = warp_sum(t);
        if (tid == 0) red[0] = t;
    }
    __syncthreads();
    const float inv = 1.0f / red[0];

    float r[8];
#pragma unroll
    for (int j = 0; j < 8; j++) r[j] = v[j] * inv;

    *reinterpret_cast<float4*>(&p[c0])     = make_float4(r[0], r[1], r[2], r[3]);
    *reinterpret_cast<float4*>(&p[c0 + 4]) = make_float4(r[4], r[5], r[6], r[7]);

    uint4 fp;
    fp.x = pack_h2(r[0], r[1]); fp.y = pack_h2(r[2], r[3]);
    fp.z = pack_h2(r[4], r[5]); fp.w = pack_h2(r[6], r[7]);
    *reinterpret_cast<uint4*>(&g_af[rowbase + c0]) = fp;
}

// ---------------------------------------------------------------------------
extern "C" void kernel_launch(void* const* d_in, const int* in_sizes, int n_in,
                              void* d_out, int out_size) {
    const float* x  = (const float*)d_in[0];   // [B,S,D]
    const float* wq = (const float*)d_in[1];   // [D,U]
    const float* wk = (const float*)d_in[2];
    const float* wv = (const float*)d_in[3];

    float* out  = (float*)d_out;
    float* ctx  = out;                         // [B,S,U]
    float* attn = out + NX;                    // [B,S,S]

    cudaFuncSetAttribute(vmt_kernel,     cudaFuncAttributeMaxDynamicSharedMemorySize, SMEM_DYN);
    cudaFuncSetAttribute(p_kernel,       cudaFuncAttributeMaxDynamicSharedMemorySize, SMEM_DYN);
    cudaFuncSetAttribute(scores_kernel,  cudaFuncAttributeMaxDynamicSharedMemorySize, SMEM_F16);
    cudaFuncSetAttribute(context_kernel, cudaFuncAttributeMaxDynamicSharedMemorySize, SMEM_F16);

    // 1. splits: x (bf16 pair + fp16), Wq/Wk (bf16 pair), Wv (transposed pair)
    split_x_kernel<<<(int)(NX / 4 / 256), 256>>>(x);
    splitW_kernel<<<dim3((int)(NW / 4 / 256), 2), 256>>>(wq, wk);
    wsplitT_kernel<<<dim3(UU / 32, DD / 32), dim3(32, 8)>>>(wv);

    // 2. V^T fp16 = (x @ Wv)^T  and  Mt = scale * Wk @ Wq^T  (one launch)
    vmt_kernel<<<dim3(528), 256, SMEM_DYN>>>();

    // 3. P fp16 = x @ Mt^T  [16384x512]
    p_kernel<<<dim3(4, 128), 256, SMEM_DYN>>>();

    // 4. scores = P @ x^T per batch (fp16 single-term; scale folded into Mt)
    scores_kernel<<<dim3(16, 16, BB), 256, SMEM_F16>>>(attn);

    // 5. softmax (fp32 out) + fp16 attn copy
    softmax_split_kernel<<<dim3(BB * SS), 256>>>(attn);

    // 6. context = attn @ V per batch (fp16 single-term)
    context_kernel<<<dim3(4, 16, BB), 256, SMEM_F16>>>(ctx);
}

// round 13
// speedup vs baseline: 2.4851x; 1.2069x over previous
#include <cuda_runtime.h>
#include <cuda_bf16.h>
#include <cuda_fp16.h>
#include <cstdint>
#include <math.h>

// Problem constants
#define BB 8
#define SS 2048
#define DD 512
#define UU 512

#define NX ((size_t)BB * SS * DD)      // 8388608
#define NW ((size_t)DD * UU)           // 262144
#define NA ((size_t)BB * SS * SS)      // 33554432

#define SCALE 0.04419417382415922f    // 1/sqrt(512)

// ---------------------------------------------------------------------------
// Device-global scratch (no allocations allowed)
// ---------------------------------------------------------------------------
__device__ __align__(128) __nv_bfloat16 g_wqh[NW], g_wql[NW];    // Wq splits [D][U] (Mt only)
__device__ __align__(128) __nv_bfloat16 g_wkh[NW], g_wkl[NW];    // Wk splits [D][U] (Mt only)
__device__ __align__(128) __half g_xf[NX];                       // x fp16 [B*S][D]
__device__ __align__(128) __half g_wvtf[NW];                     // Wv^T fp16 [U][D]
__device__ __align__(128) __half g_mtf[NW];                      // Mt fp16 [D][D] (= scale*Wk Wq^T)
__device__ __align__(128) __half g_pf[NX];                       // P fp16 [B*S][D]
__device__ __align__(128) __half g_vtf[NX];                      // V^T fp16 [B][U][S]
__device__ __align__(128) __half g_af[NA];                       // attn fp16 [B][S][S]

// ---------------------------------------------------------------------------
// Helpers
// ---------------------------------------------------------------------------
__device__ __forceinline__ uint32_t smem_u32(const void* p) {
    uint32_t a;
    asm("{ .reg .u64 t; cvta.to.shared.u64 t, %1; cvt.u32.u64 %0, t; }" : "=r"(a) : "l"(p));
    return a;
}
__device__ __forceinline__ uint32_t pack_h2(float a, float b) {
    __half2 h = __floats2half2_rn(a, b);
    return *reinterpret_cast<uint32_t*>(&h);
}

#define LDSM4(r0, r1, r2, r3, addr) \
    asm volatile("ldmatrix.sync.aligned.m8n8.x4.shared.b16 {%0,%1,%2,%3}, [%4];" \
        : "=r"(r0), "=r"(r1), "=r"(r2), "=r"(r3) : "r"(addr))

#define MMA16816(d, a, b) \
    asm("mma.sync.aligned.m16n8k16.row.col.f32.bf16.bf16.f32 " \
        "{%0,%1,%2,%3}, {%4,%5,%6,%7}, {%8,%9}, {%0,%1,%2,%3};" \
        : "+f"((d)[0]), "+f"((d)[1]), "+f"((d)[2]), "+f"((d)[3]) \
        : "r"((a)[0]), "r"((a)[1]), "r"((a)[2]), "r"((a)[3]), \
          "r"((b)[0]), "r"((b)[1]))

#define MMAH16816(d, a, b) \
    asm("mma.sync.aligned.m16n8k16.row.col.f32.f16.f16.f32 " \
        "{%0,%1,%2,%3}, {%4,%5,%6,%7}, {%8,%9}, {%0,%1,%2,%3};" \
        : "+f"((d)[0]), "+f"((d)[1]), "+f"((d)[2]), "+f"((d)[3]) \
        : "r"((a)[0]), "r"((a)[1]), "r"((a)[2]), "r"((a)[3]), \
          "r"((b)[0]), "r"((b)[1]))

// ---------------------------------------------------------------------------
// Common tiling: 128x128 CTA tile, BK=32, 256 threads (8 warps 2x4, 64x32
// warp tile), 3-stage cp.async pipeline, 2 CTAs/SM.  64B smem rows, XOR
// swizzle phys_chunk = c ^ ((r>>1)&3).  Operands K-major; C = A * B^T.
// ---------------------------------------------------------------------------
#define ARR_B 8192                      // 128 rows * 64 bytes per array
#define STG_B 32768                     // 4 arrays per stage (bf16x3 engine)
#define SMEM_DYN (3 * STG_B)            // 98304 bytes
#define STGF_B 16384                    // 2 arrays per stage (fp16 engine)
#define SMEM_F16 (3 * STGF_B)           // 49152 bytes

template <typename T>
__device__ __forceinline__ void stage_arr(uint32_t sdst, const T* __restrict__ src,
                                          int r0, int k0, int ld, int tid) {
#pragma unroll
    for (int j = 0; j < 2; j++) {
        int idx = tid + j * 256;                  // 512 chunks of 16B
        int r = idx >> 2, c = idx & 3;
        int phys = c ^ ((r >> 1) & 3);
        uint32_t dst = sdst + (uint32_t)(r * 64 + phys * 16);
        const void* gp = (const void*)(src + (size_t)(r0 + r) * ld + k0 + c * 8);
        asm volatile("cp.async.cg.shared.global [%0], [%1], 16;" :: "r"(dst), "l"(gp));
    }
}

// ---------------------------------------------------------------------------
// bf16x3 engine — used ONLY for Mt (16 blocks).  fp16-out with alpha.
// ---------------------------------------------------------------------------
__device__ __forceinline__ void gemm_bf3(int row0, int col0,
                                         const __nv_bfloat16* __restrict__ Ah,
                                         const __nv_bfloat16* __restrict__ Al,
                                         const __nv_bfloat16* __restrict__ Bh,
                                         const __nv_bfloat16* __restrict__ Bl,
                                         int K, int lda, int ldb, float alpha,
                                         __half* __restrict__ Of, int ldo) {
    extern __shared__ __nv_bfloat16 smem[];

    const int tid  = threadIdx.x;
    const int warp = tid >> 5;
    const int lane = tid & 31;
    const int wm = (warp >> 2) * 64;
    const int wn = (warp & 3) * 32;

    const uint32_t sbase = smem_u32(smem);

    const int aRow = wm + ((lane >> 3) & 1) * 8 + (lane & 7);
    const uint32_t aOff = (uint32_t)(aRow * 64);
    const uint32_t aS   = (uint32_t)((aRow >> 1) & 3);
    const uint32_t aK   = (uint32_t)(lane >> 4);
    const int bRow = wn + ((lane >> 4) & 1) * 8 + (lane & 7);
    const uint32_t bOff = (uint32_t)(bRow * 64);
    const uint32_t bS   = (uint32_t)((bRow >> 1) & 3);
    const uint32_t bK   = (uint32_t)((lane >> 3) & 1);

    float acc[4][4][4];
#pragma unroll
    for (int i = 0; i < 4; i++)
#pragma unroll
        for (int j = 0; j < 4; j++)
#pragma unroll
            for (int e = 0; e < 4; e++) acc[i][j][e] = 0.0f;

    const int niter = K >> 5;

    // prologue: stage iters 0,1
#pragma unroll
    for (int s = 0; s < 2; s++) {
        uint32_t sb = sbase + (uint32_t)(s * STG_B);
        stage_arr(sb + 0 * ARR_B, Ah, row0, s * 32, lda, tid);
        stage_arr(sb + 1 * ARR_B, Al, row0, s * 32, lda, tid);
        stage_arr(sb + 2 * ARR_B, Bh, col0, s * 32, ldb, tid);
        stage_arr(sb + 3 * ARR_B, Bl, col0, s * 32, ldb, tid);
        asm volatile("cp.async.commit_group;" ::: "memory");
    }

    int buf = 0;
    for (int it = 0; it < niter; it++) {
        if (it + 1 < niter) {
            asm volatile("cp.async.wait_group 1;" ::: "memory");
        } else {
            asm volatile("cp.async.wait_group 0;" ::: "memory");
        }
        __syncthreads();
        if (it + 2 < niter) {
            int nb = buf + 2; if (nb >= 3) nb -= 3;
            uint32_t sb = sbase + (uint32_t)(nb * STG_B);
            int k0 = (it + 2) << 5;
            stage_arr(sb + 0 * ARR_B, Ah, row0, k0, lda, tid);
            stage_arr(sb + 1 * ARR_B, Al, row0, k0, lda, tid);
            stage_arr(sb + 2 * ARR_B, Bh, col0, k0, ldb, tid);
            stage_arr(sb + 3 * ARR_B, Bl, col0, k0, ldb, tid);
            asm volatile("cp.async.commit_group;" ::: "memory");
        }

        const uint32_t base = sbase + (uint32_t)(buf * STG_B);
        const uint32_t pAh = base + 0 * ARR_B + aOff;
        const uint32_t pAl = base + 1 * ARR_B + aOff;
        const uint32_t pBh = base + 2 * ARR_B + bOff;
        const uint32_t pBl = base + 3 * ARR_B + bOff;

#pragma unroll
        for (int ks = 0; ks < 2; ks++) {
            const uint32_t koA = (((ks * 2 + aK) ^ aS) << 4);
            const uint32_t koB = (((ks * 2 + bK) ^ bS) << 4);
            uint32_t ah[4][4], al[4][4];
            uint32_t bh[4][2], bl[4][2];
#pragma unroll
            for (int jp = 0; jp < 2; jp++) {
                LDSM4(bh[2 * jp][0], bh[2 * jp][1], bh[2 * jp + 1][0], bh[2 * jp + 1][1],
                      pBh + jp * 1024 + koB);
                LDSM4(bl[2 * jp][0], bl[2 * jp][1], bl[2 * jp + 1][0], bl[2 * jp + 1][1],
                      pBl + jp * 1024 + koB);
            }
#pragma unroll
            for (int i = 0; i < 4; i++) {
                LDSM4(ah[i][0], ah[i][1], ah[i][2], ah[i][3], pAh + i * 1024 + koA);
                LDSM4(al[i][0], al[i][1], al[i][2], al[i][3], pAl + i * 1024 + koA);
            }
#pragma unroll
            for (int i = 0; i < 4; i++)
#pragma unroll
                for (int j = 0; j < 4; j++) MMA16816(acc[i][j], ah[i], bh[j]);
#pragma unroll
            for (int i = 0; i < 4; i++)
#pragma unroll
                for (int j = 0; j < 4; j++) MMA16816(acc[i][j], ah[i], bl[j]);
#pragma unroll
            for (int i = 0; i < 4; i++)
#pragma unroll
                for (int j = 0; j < 4; j++) MMA16816(acc[i][j], al[i], bh[j]);
        }
        buf++; if (buf == 3) buf = 0;
    }

    // epilogue: fp16 direct store (alpha-scaled)
    const int er = lane >> 2;
    const int ec = (lane & 3) * 2;
#pragma unroll
    for (int i = 0; i < 4; i++)
#pragma unroll
        for (int j = 0; j < 4; j++) {
            size_t r = (size_t)(row0 + wm + i * 16 + er);
            int c = col0 + wn + j * 8 + ec;
            *reinterpret_cast<uint32_t*>(&Of[r * ldo + c]) =
                pack_h2(acc[i][j][0] * alpha, acc[i][j][1] * alpha);
            *reinterpret_cast<uint32_t*>(&Of[(r + 8) * ldo + c]) =
                pack_h2(acc[i][j][2] * alpha, acc[i][j][3] * alpha);
        }
}

// ---------------------------------------------------------------------------
// fp16 single-term engine.  MODE 0: fp32 store.  MODE 3: fp16 direct store.
// MODE 4: fp16 TRANSPOSED store (per-batch V^T layout, ldo = SS).
// ---------------------------------------------------------------------------
template <int MODE>
__device__ __forceinline__ void gemm_f16(int row0, int col0,
                                         const __half* __restrict__ Af,
                                         const __half* __restrict__ Bf,
                                         int K, int lda, int ldb,
                                         float* __restrict__ Cf, int ldc,
                                         __half* __restrict__ Of, int ldo) {
    extern __shared__ __nv_bfloat16 smem[];

    const int tid  = threadIdx.x;
    const int warp = tid >> 5;
    const int lane = tid & 31;
    const int wm = (warp >> 2) * 64;
    const int wn = (warp & 3) * 32;

    const uint32_t sbase = smem_u32(smem);

    const int aRow = wm + ((lane >> 3) & 1) * 8 + (lane & 7);
    const uint32_t aOff = (uint32_t)(aRow * 64);
    const uint32_t aS   = (uint32_t)((aRow >> 1) & 3);
    const uint32_t aK   = (uint32_t)(lane >> 4);
    const int bRow = wn + ((lane >> 4) & 1) * 8 + (lane & 7);
    const uint32_t bOff = (uint32_t)(bRow * 64);
    const uint32_t bS   = (uint32_t)((bRow >> 1) & 3);
    const uint32_t bK   = (uint32_t)((lane >> 3) & 1);

    float acc[4][4][4];
#pragma unroll
    for (int i = 0; i < 4; i++)
#pragma unroll
        for (int j = 0; j < 4; j++)
#pragma unroll
            for (int e = 0; e < 4; e++) acc[i][j][e] = 0.0f;

    const int niter = K >> 5;

    // prologue: stage iters 0,1
#pragma unroll
    for (int s = 0; s < 2; s++) {
        uint32_t sb = sbase + (uint32_t)(s * STGF_B);
        stage_arr(sb + 0 * ARR_B, Af, row0, s * 32, lda, tid);
        stage_arr(sb + 1 * ARR_B, Bf, col0, s * 32, ldb, tid);
        asm volatile("cp.async.commit_group;" ::: "memory");
    }

    int buf = 0;
    for (int it = 0; it < niter; it++) {
        if (it + 1 < niter) {
            asm volatile("cp.async.wait_group 1;" ::: "memory");
        } else {
            asm volatile("cp.async.wait_group 0;" ::: "memory");
        }
        __syncthreads();
        if (it + 2 < niter) {
            int nb = buf + 2; if (nb >= 3) nb -= 3;
            uint32_t sb = sbase + (uint32_t)(nb * STGF_B);
            int k0 = (it + 2) << 5;
            stage_arr(sb + 0 * ARR_B, Af, row0, k0, lda, tid);
            stage_arr(sb + 1 * ARR_B, Bf, col0, k0, ldb, tid);
            asm volatile("cp.async.commit_group;" ::: "memory");
        }

        const uint32_t base = sbase + (uint32_t)(buf * STGF_B);
        const uint32_t pA = base + 0 * ARR_B + aOff;
        const uint32_t pB = base + 1 * ARR_B + bOff;

#pragma unroll
        for (int ks = 0; ks < 2; ks++) {
            const uint32_t koA = (((ks * 2 + aK) ^ aS) << 4);
            const uint32_t koB = (((ks * 2 + bK) ^ bS) << 4);
            uint32_t ah[4][4];
            uint32_t bh[4][2];
#pragma unroll
            for (int jp = 0; jp < 2; jp++) {
                LDSM4(bh[2 * jp][0], bh[2 * jp][1], bh[2 * jp + 1][0], bh[2 * jp + 1][1],
                      pB + jp * 1024 + koB);
            }
#pragma unroll
            for (int i = 0; i < 4; i++) {
                LDSM4(ah[i][0], ah[i][1], ah[i][2], ah[i][3], pA + i * 1024 + koA);
            }
#pragma unroll
            for (int i = 0; i < 4; i++)
#pragma unroll
                for (int j = 0; j < 4; j++) MMAH16816(acc[i][j], ah[i], bh[j]);
        }
        buf++; if (buf == 3) buf = 0;
    }

    // ------------------------- epilogue -------------------------
    const int er = lane >> 2;
    const int ec = (lane & 3) * 2;

    if constexpr (MODE == 0) {
#pragma unroll
        for (int i = 0; i < 4; i++)
#pragma unroll
            for (int j = 0; j < 4; j++) {
                size_t r = (size_t)(row0 + wm + i * 16 + er);
                int c = col0 + wn + j * 8 + ec;
                *reinterpret_cast<float2*>(&Cf[r * ldc + c]) =
                    make_float2(acc[i][j][0], acc[i][j][1]);
                *reinterpret_cast<float2*>(&Cf[(r + 8) * ldc + c]) =
                    make_float2(acc[i][j][2], acc[i][j][3]);
            }
    } else if constexpr (MODE == 3) {
#pragma unroll
        for (int i = 0; i < 4; i++)
#pragma unroll
            for (int j = 0; j < 4; j++) {
                size_t r = (size_t)(row0 + wm + i * 16 + er);
                int c = col0 + wn + j * 8 + ec;
                *reinterpret_cast<uint32_t*>(&Of[r * ldo + c]) =
                    pack_h2(acc[i][j][0], acc[i][j][1]);
                *reinterpret_cast<uint32_t*>(&Of[(r + 8) * ldo + c]) =
                    pack_h2(acc[i][j][2], acc[i][j][3]);
            }
    } else {
        // MODE 4: fp16 transposed store (V^T); row0 indexes tokens [B*S]
        __syncthreads();   // pipeline smem reuse
        float* ew = (float*)(smem + warp * 768);   // 16x24 floats per warp
        const int b = row0 >> 11;                  // SS == 2048
        __half* Ob = Of + (size_t)b * UU * SS;
#pragma unroll
        for (int i = 0; i < 4; i++)
#pragma unroll
            for (int jp = 0; jp < 2; jp++) {
                int j0 = 2 * jp, j1 = 2 * jp + 1;
                ew[er * 24 + ec]            = acc[i][j0][0];
                ew[er * 24 + ec + 1]        = acc[i][j0][1];
                ew[(er + 8) * 24 + ec]      = acc[i][j0][2];
                ew[(er + 8) * 24 + ec + 1]  = acc[i][j0][3];
                ew[er * 24 + 8 + ec]        = acc[i][j1][0];
                ew[er * 24 + 8 + ec + 1]    = acc[i][j1][1];
                ew[(er + 8) * 24 + 8 + ec]     = acc[i][j1][2];
                ew[(er + 8) * 24 + 8 + ec + 1] = acc[i][j1][3];
                __syncwarp();
                if (lane < 16) {
                    int u = lane;
                    float v[16];
#pragma unroll
                    for (int r = 0; r < 16; r++) v[r] = ew[r * 24 + u];
                    uint32_t hw[8];
#pragma unroll
                    for (int e = 0; e < 8; e++) hw[e] = pack_h2(v[2 * e], v[2 * e + 1]);
                    int s0 = (row0 & 2047) + wm + i * 16;
                    size_t idx = (size_t)(col0 + wn + jp * 16 + u) * SS + s0;
                    uint4 h0, h1;
                    h0.x = hw[0]; h0.y = hw[1]; h0.z = hw[2]; h0.w = hw[3];
                    h1.x = hw[4]; h1.y = hw[5]; h1.z = hw[6]; h1.w = hw[7];
                    *reinterpret_cast<uint4*>(&Ob[idx])     = h0;
                    *reinterpret_cast<uint4*>(&Ob[idx + 8]) = h1;
                }
                __syncwarp();
            }
    }
}

// ---------------------------------------------------------------------------
// GEMM kernel wrappers (2 CTAs/SM)
// ---------------------------------------------------------------------------

// Combined: V^T fp16 projection (blocks 0..511) + Mt bf16x3 (blocks 512..527).
__global__ __launch_bounds__(256, 2) void vmt_kernel() {
    int id = blockIdx.x;
    if (id < 512) {
        int row0 = (id >> 2) * 128;       // token tile
        int col0 = (id & 3) * 128;        // u tile
        gemm_f16<4>(row0, col0, g_xf, g_wvtf, DD, DD, DD,
                    nullptr, 0, g_vtf, SS);
    } else {
        int id2 = id - 512;
        int row0 = (id2 >> 2) * 128;
        int col0 = (id2 & 3) * 128;
        gemm_bf3(row0, col0, g_wkh, g_wkl, g_wqh, g_wql, UU, UU, UU, SCALE,
                 g_mtf, DD);
    }
}

__global__ __launch_bounds__(256, 2) void p_kernel() {
    // P fp16 = x @ Mt^T  [B*S][D]
    gemm_f16<3>(blockIdx.y * 128, blockIdx.x * 128,
                g_xf, g_mtf, DD, DD, DD,
                nullptr, 0, g_pf, DD);
}

__global__ __launch_bounds__(256, 2) void scores_kernel(float* __restrict__ attn) {
    const size_t zo = (size_t)blockIdx.z * SS * DD;
    gemm_f16<0>(blockIdx.y * 128, blockIdx.x * 128,
                g_pf + zo, g_xf + zo, DD, DD, DD,
                attn + (size_t)blockIdx.z * SS * SS, SS, nullptr, 0);
}

__global__ __launch_bounds__(256, 2) void context_kernel(float* __restrict__ ctx) {
    const size_t z = blockIdx.z;
    gemm_f16<0>(blockIdx.y * 128, blockIdx.x * 128,
                g_af + z * (size_t)SS * SS, g_vtf + z * (size_t)UU * SS,
                SS, SS, SS,
                ctx + z * (size_t)SS * UU, UU, nullptr, 0);
}

// ---------------------------------------------------------------------------
// Elementwise kernels
// ---------------------------------------------------------------------------
__global__ __launch_bounds__(256) void split_x_kernel(const float* __restrict__ in) {
    int i = blockIdx.x * 256 + threadIdx.x;     // float4 granules, NX/4 total
    float4 v = reinterpret_cast<const float4*>(in)[i];
    uint2 fp;
    fp.x = pack_h2(v.x, v.y);
    fp.y = pack_h2(v.z, v.w);
    reinterpret_cast<uint2*>(g_xf)[i] = fp;
}

__device__ __forceinline__ uint32_t pack_bf2(__nv_bfloat16 a, __nv_bfloat16 b) {
    return (uint32_t)__bfloat16_as_ushort(a) | ((uint32_t)__bfloat16_as_ushort(b) << 16);
}

__global__ __launch_bounds__(256) void splitW_kernel(const float* __restrict__ wq,
                                                     const float* __restrict__ wk) {
    const float* src = (blockIdx.y == 0) ? wq : wk;
    __nv_bfloat16* oh = (blockIdx.y == 0) ? g_wqh : g_wkh;
    __nv_bfloat16* ol = (blockIdx.y == 0) ? g_wql : g_wkl;
    int i = blockIdx.x * 256 + threadIdx.x;     // NW/4 granules
    float4 v = reinterpret_cast<const float4*>(src)[i];
    __nv_bfloat16 h0 = __float2bfloat16(v.x), h1 = __float2bfloat16(v.y);
    __nv_bfloat16 h2 = __float2bfloat16(v.z), h3 = __float2bfloat16(v.w);
    uint2 hp, lp;
    hp.x = pack_bf2(h0, h1); hp.y = pack_bf2(h2, h3);
    lp.x = pack_bf2(__float2bfloat16(v.x - __bfloat162float(h0)),
                    __float2bfloat16(v.y - __bfloat162float(h1)));
    lp.y = pack_bf2(__float2bfloat16(v.z - __bfloat162float(h2)),
                    __float2bfloat16(v.w - __bfloat162float(h3)));
    reinterpret_cast<uint2*>(oh)[i] = hp;
    reinterpret_cast<uint2*>(ol)[i] = lp;
}

__global__ void wsplitT_kernel(const float* __restrict__ wv) {
    __shared__ float t[32][33];
    const int u0 = blockIdx.x * 32, d0 = blockIdx.y * 32;
    const int tx = threadIdx.x, ty = threadIdx.y;
#pragma unroll
    for (int p = 0; p < 4; p++)
        t[ty + p * 8][tx] = wv[(size_t)(d0 + ty + p * 8) * UU + u0 + tx];
    __syncthreads();
#pragma unroll
    for (int p = 0; p < 4; p++) {
        float v = t[tx][ty + p * 8];
        size_t idx = (size_t)(u0 + ty + p * 8) * DD + d0 + tx;
        g_wvtf[idx] = __float2half_rn(v);
    }
}

__device__ __forceinline__ float warp_max(float v) {
#pragma unroll
    for (int o = 16; o > 0; o >>= 1) v = fmaxf(v, __shfl_xor_sync(0xffffffffu, v, o));
    return v;
}
__device__ __forceinline__ float warp_sum(float v) {
#pragma unroll
    for (int o = 16; o > 0; o >>= 1) v += __shfl_xor_sync(0xffffffffu, v, o);
    return v;
}

// Row softmax + fp16 store, vectorized: thread t owns 8 contiguous columns.
__global__ __launch_bounds__(256) void softmax_split_kernel(float* __restrict__ attn) {
    const size_t rowbase = (size_t)blockIdx.x * SS;
    float* p = attn + rowbase;
    const int tid = threadIdx.x;
    const int c0 = tid * 8;
    __shared__ float red[8];

    float4 va = *reinterpret_cast<const float4*>(&p[c0]);
    float4 vb = *reinterpret_cast<const float4*>(&p[c0 + 4]);
    float v[8] = {va.x, va.y, va.z, va.w, vb.x, vb.y, vb.z, vb.w};

    float m = v[0];
#pragma unroll
    for (int j = 1; j < 8; j++) m = fmaxf(m, v[j]);
    m = warp_max(m);
    if ((tid & 31) == 0) red[tid >> 5] = m;
    __syncthreads();
    if (tid < 32) {
        float t = (tid < 8) ? red[tid] : -INFINITY;
        t = warp_max(t);
        if (tid == 0) red[0] = t;
    }
    __syncthreads();
    m = red[0];

    float s = 0.0f;
#pragma unroll
    for (int j = 0; j < 8; j++) { v[j] = __expf(v[j] - m); s += v[j]; }
    s = warp_sum(s);
    __syncthreads();
    if ((tid & 31) == 0) red[tid >> 5] = s;
    __syncthreads();
    if (tid < 32) {
        float t = (tid < 8) ? red[tid] : 0.0f;
        t = warp_sum(t);
        if (tid == 0) red[0] = t;
    }
    __syncthreads();
    const float inv = 1.0f / red[0];

    float r[8];
#pragma unroll
    for (int j = 0; j < 8; j++) r[j] = v[j] * inv;

    *reinterpret_cast<float4*>(&p[c0])     = make_float4(r[0], r[1], r[2], r[3]);
    *reinterpret_cast<float4*>(&p[c0 + 4]) = make_float4(r[4], r[5], r[6], r[7]);

    uint4 fp;
    fp.x = pack_h2(r[0], r[1]); fp.y = pack_h2(r[2], r[3]);
    fp.z = pack_h2(r[4], r[5]); fp.w = pack_h2(r[6], r[7]);
    *reinterpret_cast<uint4*>(&g_af[rowbase + c0]) = fp;
}

// ---------------------------------------------------------------------------
extern "C" void kernel_launch(void* const* d_in, const int* in_sizes, int n_in,
                              void* d_out, int out_size) {
    const float* x  = (const float*)d_in[0];   // [B,S,D]
    const float* wq = (const float*)d_in[1];   // [D,U]
    const float* wk = (const float*)d_in[2];
    const float* wv = (const float*)d_in[3];

    float* out  = (float*)d_out;
    float* ctx  = out;                         // [B,S,U]
    float* attn = out + NX;                    // [B,S,S]

    cudaFuncSetAttribute(vmt_kernel,     cudaFuncAttributeMaxDynamicSharedMemorySize, SMEM_DYN);
    cudaFuncSetAttribute(p_kernel,       cudaFuncAttributeMaxDynamicSharedMemorySize, SMEM_F16);
    cudaFuncSetAttribute(scores_kernel,  cudaFuncAttributeMaxDynamicSharedMemorySize, SMEM_F16);
    cudaFuncSetAttribute(context_kernel, cudaFuncAttributeMaxDynamicSharedMemorySize, SMEM_F16);

    // 1. splits: x -> fp16, Wq/Wk -> bf16 pairs (Mt only), Wv -> fp16 transposed
    split_x_kernel<<<(int)(NX / 4 / 256), 256>>>(x);
    splitW_kernel<<<dim3((int)(NW / 4 / 256), 2), 256>>>(wq, wk);
    wsplitT_kernel<<<dim3(UU / 32, DD / 32), dim3(32, 8)>>>(wv);

    // 2. V^T fp16 = (x @ Wv)^T  and  Mt fp16 = scale * Wk @ Wq^T (bf16x3 math)
    vmt_kernel<<<dim3(528), 256, SMEM_DYN>>>();

    // 3. P fp16 = x @ Mt^T  [16384x512]
    p_kernel<<<dim3(4, 128), 256, SMEM_F16>>>();

    // 4. scores = P @ x^T per batch (fp16; scale folded into Mt)
    scores_kernel<<<dim3(16, 16, BB), 256, SMEM_F16>>>(attn);

    // 5. softmax (fp32 out) + fp16 attn copy
    softmax_split_kernel<<<dim3(BB * SS), 256>>>(attn);

    // 6. context = attn @ V per batch (fp16)
    context_kernel<<<dim3(4, 16, BB), 256, SMEM_F16>>>(ctx);
}